// round 9
// baseline (speedup 1.0000x reference)
#include <cuda_runtime.h>
#include <cstdint>

// ---------------------------------------------------------------------------
// out = sx*sy * ( X@Y - zpy*rowsum(X)[m] - zpx*colsum(Y)[n] + K*zpx*zpy )
// Inputs are INT32 (harness canonical dtype), values in [-128,127].
// Prepass packs into tile-major PRE-SWIZZLED 8KB slabs:
//   g_xa[mtile][kt] : A slab = smem image of X[m0:m0+128, kt*64:kt*64+64]
//   g_yb[ntile][kt] : B slab = smem image of Y^T[n0:n0+128, kt*64:kt*64+64]
// GEMM stages load with cp.async.bulk (2 x 8KB per stage, mbarrier expect_tx).
// S exact in s32 via mma.sync m16n8k32 (IMMA) + ldmatrix.x4 (proven mapping).
// ---------------------------------------------------------------------------

static constexpr int MD = 4096, KD = 4096, ND = 4096;
static constexpr float KZZf = -1843200.0f;     // K*zpx*zpy = 4096*(-25)*18
static constexpr float SXY  = 0.0215f * 0.0176f;

__device__ int8_t g_xa[(size_t)MD * KD];       // 16MB tiled swizzled X
__device__ int8_t g_yb[(size_t)ND * KD];       // 16MB tiled swizzled Y^T
__device__ int    g_rxs[MD];                   // rowsum_x (exact int)
__device__ int    g_cys[ND];                   // colsum_y (exact int)
__device__ float  g_rxf[MD];                   // -18 * rowsum
__device__ float  g_cyf[ND];                   // +25 * colsum + KZZ

// ------------------------------ helpers -----------------------------------

__device__ __forceinline__ uint32_t smem_u32(const void* p) {
    uint32_t a;
    asm("{ .reg .u64 t; cvta.to.shared.u64 t, %1; cvt.u32.u64 %0, t; }"
        : "=r"(a) : "l"(p));
    return a;
}

#define MBARRIER_INIT(addr, cnt) \
    asm volatile("mbarrier.init.shared.b64 [%0], %1;" :: "r"(addr), "r"(cnt) : "memory")

#define MBARRIER_EXPECT_TX(addr, bytes) \
    asm volatile("mbarrier.arrive.expect_tx.shared.b64 _, [%0], %1;" \
                 :: "r"(addr), "r"(bytes) : "memory")

#define MBARRIER_WAIT_PARITY(addr, ph) do {                                         \
    uint32_t _m = (uint32_t)(addr); uint32_t _p = (uint32_t)(ph); uint32_t _d;      \
    asm volatile("{\n\t.reg .pred p;\n\t"                                           \
        "mbarrier.try_wait.parity.acquire.cta.shared::cta.b64 p, [%1], %2;\n\t"     \
        "selp.b32 %0, 1, 0, p;\n\t}"                                                \
        : "=r"(_d) : "r"(_m), "r"(_p) : "memory");                                  \
    if (!_d) {                                                                      \
        asm volatile("{\n\t.reg .pred P1;\n\t"                                      \
            "WL%=:\n\t"                                                             \
            "mbarrier.try_wait.parity.acquire.cta.shared::cta.b64 P1, [%0], %1, 0x989680;\n\t" \
            "@P1 bra.uni WD%=;\n\t"                                                 \
            "bra.uni WL%=;\n\t"                                                     \
            "WD%=:\n\t}"                                                            \
            :: "r"(_m), "r"(_p) : "memory");                                        \
    } } while (0)

__device__ __forceinline__ void bulk_g2s(uint32_t dst, const void* src,
                                         uint32_t bytes, uint32_t mbar) {
    asm volatile(
        "cp.async.bulk.shared::cluster.global.mbarrier::complete_tx::bytes "
        "[%0], [%1], %2, [%3];"
        :: "r"(dst), "l"(src), "r"(bytes), "r"(mbar) : "memory");
}

#define LDSM4(r0, r1, r2, r3, addr) \
    asm volatile("ldmatrix.sync.aligned.m8n8.x4.shared.b16 {%0,%1,%2,%3}, [%4];" \
                 : "=r"(r0), "=r"(r1), "=r"(r2), "=r"(r3) : "r"(addr))

#define MMA_S8(d, a0, a1, a2, a3, b0, b1) \
    asm volatile("mma.sync.aligned.m16n8k32.row.col.s32.s8.s8.s32 " \
                 "{%0,%1,%2,%3},{%4,%5,%6,%7},{%8,%9},{%0,%1,%2,%3};" \
                 : "+r"((d)[0]), "+r"((d)[1]), "+r"((d)[2]), "+r"((d)[3]) \
                 : "r"(a0), "r"(a1), "r"(a2), "r"(a3), "r"(b0), "r"(b1))

// smem tile layout: 128 rows x 64B, XOR-swizzled over 128B lines (8x16B slots)
__device__ __forceinline__ uint32_t sw_off(int r, int c) {
    int line = r >> 1;
    int slot = (((r & 1) * 4 + c) ^ (line & 7));
    return (uint32_t)(line * 128 + slot * 16);
}

// slab byte offset for element (row r 0..127, col c 0..63) -- char4 aligned
__device__ __forceinline__ uint32_t slab_off(int r, int c) {
    return sw_off(r, c >> 4) + (c & 15);
}

// ------------------------------ prepasses ---------------------------------

__global__ void k_zero_sums() {
    int i = blockIdx.x * 256 + threadIdx.x;
    g_rxs[i] = 0;
    g_cys[i] = 0;
}

// X int32 -> tiled swizzled int8 slabs + rowsum (exact int atomics)
__global__ void k_pack_x(const int4* __restrict__ q) {
    size_t i = (size_t)blockIdx.x * 256 + threadIdx.x;
    int4 v = q[i];
    char4 c;
    c.x = (char)v.x; c.y = (char)v.y; c.z = (char)v.z; c.w = (char)v.w;
    size_t e = i * 4;
    int m = (int)(e >> 12);
    int k = (int)(e & 4095);
    size_t dst = ((size_t)(m >> 7) * 64 + (k >> 6)) * 8192 + slab_off(m & 127, k & 63);
    *(char4*)(g_xa + dst) = c;

    int w; memcpy(&w, &c, 4);
    int part = __dp4a(w, 0x01010101, 0);
#pragma unroll
    for (int s = 16; s; s >>= 1) part += __shfl_xor_sync(0xffffffffu, part, s);
    if ((threadIdx.x & 31) == 0) atomicAdd(&g_rxs[m], part);   // warp spans one row
}

// Y int32 [K,N] -> transposed tiled swizzled slabs + colsum
__global__ void k_pack_y(const int* __restrict__ Y) {
    __shared__ int8_t tile[32][36];
    int n0 = blockIdx.x * 32, k0 = blockIdx.y * 32;
    int t = threadIdx.x;
    {
        int k = t >> 3, nq = (t & 7) * 4;
        int4 v = *(const int4*)(Y + (size_t)(k0 + k) * ND + n0 + nq);
        tile[nq + 0][k] = (int8_t)v.x;
        tile[nq + 1][k] = (int8_t)v.y;
        tile[nq + 2][k] = (int8_t)v.z;
        tile[nq + 3][k] = (int8_t)v.w;
    }
    __syncthreads();
    {
        int nl = t >> 3, kq = (t & 7) * 4;
        char4 c;
        c.x = tile[nl][kq + 0]; c.y = tile[nl][kq + 1];
        c.z = tile[nl][kq + 2]; c.w = tile[nl][kq + 3];
        int n = n0 + nl, k = k0 + kq;
        size_t dst = ((size_t)(n >> 7) * 64 + (k >> 6)) * 8192 + slab_off(n & 127, k & 63);
        *(char4*)(g_yb + dst) = c;

        int w; memcpy(&w, &c, 4);
        int part = __dp4a(w, 0x01010101, 0);
        part += __shfl_xor_sync(0xffffffffu, part, 1);
        part += __shfl_xor_sync(0xffffffffu, part, 2);
        part += __shfl_xor_sync(0xffffffffu, part, 4);
        if ((t & 7) == 0) atomicAdd(&g_cys[n], part);
    }
}

__global__ void k_finalize() {
    int i = blockIdx.x * 256 + threadIdx.x;
    g_rxf[i] = -18.0f * (float)g_rxs[i];
    g_cyf[i] = 25.0f * (float)g_cys[i] + KZZf;
}

// ------------------------------- GEMM -------------------------------------
// CTA 128x128, K-stage 64, 4 stages loaded via cp.async.bulk (2 x 8KB each).
// 256 threads = 8 warps (4 M x 2 N), warp tile 32x64.

static constexpr int STAGES = 4;
static constexpr int STAGE_BYTES = 16384;
static constexpr int STAGE0_OFF = 1024;
static constexpr int SMEM_TOTAL = STAGE0_OFF + STAGES * STAGE_BYTES;  // 66560
static constexpr int KITERS = KD / 64;                                // 64

__global__ void __launch_bounds__(256)
gemm_i8_kernel(float* __restrict__ OUT) {
    extern __shared__ char smem[];
    const uint32_t sbase = smem_u32(smem);
    const uint32_t stg = sbase + STAGE0_OFF;
    const int tid = threadIdx.x;
    const int lane = tid & 31;
    const int wid = tid >> 5;
    const int wm = wid & 3;
    const int wn = wid >> 2;
    const int m0 = blockIdx.y * 128;
    const int n0 = blockIdx.x * 128;

    const int sel = lane >> 3;
    const int l7  = lane & 7;

    const int8_t* aslab = g_xa + (size_t)(m0 >> 7) * 64 * 8192;
    const int8_t* bslab = g_yb + (size_t)(n0 >> 7) * 64 * 8192;

    if (tid == 0) {
#pragma unroll
        for (int s = 0; s < STAGES; s++) MBARRIER_INIT(sbase + s * 8, 1);
        asm volatile("fence.proxy.async.shared::cta;" ::: "memory");
    }
    __syncthreads();

    if (tid == 0) {
#pragma unroll
        for (int p = 0; p < STAGES; p++) {
            MBARRIER_EXPECT_TX(sbase + p * 8, STAGE_BYTES);
            bulk_g2s(stg + p * STAGE_BYTES,        aslab + (size_t)p * 8192, 8192, sbase + p * 8);
            bulk_g2s(stg + p * STAGE_BYTES + 8192, bslab + (size_t)p * 8192, 8192, sbase + p * 8);
        }
    }

    int acc[2][8][4];
#pragma unroll
    for (int i = 0; i < 2; i++)
#pragma unroll
        for (int j = 0; j < 8; j++)
#pragma unroll
            for (int q = 0; q < 4; q++) acc[i][j][q] = 0;

    for (int it = 0; it < KITERS; it++) {
        const int s = it & 3;
        MBARRIER_WAIT_PARITY(sbase + s * 8, (it >> 2) & 1);

        const uint32_t sA = stg + s * STAGE_BYTES;
        const uint32_t sB = sA + 8192;

        // ---- front-batched fragment loads: 12 LDSM4 ----
        uint32_t a[2][2][4];       // [ks][mt]
        uint32_t b[2][4][4];       // [ks][p]
#pragma unroll
        for (int ks = 0; ks < 2; ks++)
#pragma unroll
            for (int mt = 0; mt < 2; mt++) {
                int row = wm * 32 + mt * 16 + l7 + (sel & 1) * 8;
                int ch  = 2 * ks + (sel >> 1);
                LDSM4(a[ks][mt][0], a[ks][mt][1], a[ks][mt][2], a[ks][mt][3],
                      sA + sw_off(row, ch));
            }
#pragma unroll
        for (int ks = 0; ks < 2; ks++)
#pragma unroll
            for (int p = 0; p < 4; p++) {
                int nt  = p * 2 + (sel >> 1);
                int row = wn * 64 + nt * 8 + l7;
                int ch  = 2 * ks + (sel & 1);
                LDSM4(b[ks][p][0], b[ks][p][1], b[ks][p][2], b[ks][p][3],
                      sB + sw_off(row, ch));
            }

        // ---- 32 IMMA ----
#pragma unroll
        for (int ks = 0; ks < 2; ks++)
#pragma unroll
            for (int p = 0; p < 4; p++) {
                MMA_S8(acc[0][p * 2 + 0], a[ks][0][0], a[ks][0][1], a[ks][0][2], a[ks][0][3],
                       b[ks][p][0], b[ks][p][1]);
                MMA_S8(acc[0][p * 2 + 1], a[ks][0][0], a[ks][0][1], a[ks][0][2], a[ks][0][3],
                       b[ks][p][2], b[ks][p][3]);
                MMA_S8(acc[1][p * 2 + 0], a[ks][1][0], a[ks][1][1], a[ks][1][2], a[ks][1][3],
                       b[ks][p][0], b[ks][p][1]);
                MMA_S8(acc[1][p * 2 + 1], a[ks][1][0], a[ks][1][1], a[ks][1][2], a[ks][1][3],
                       b[ks][p][2], b[ks][p][3]);
            }

        __syncthreads();                       // all warps done with stage s
        if (tid == 0 && it + 4 < KITERS) {
            MBARRIER_EXPECT_TX(sbase + s * 8, STAGE_BYTES);
            bulk_g2s(stg + s * STAGE_BYTES,        aslab + (size_t)(it + 4) * 8192, 8192, sbase + s * 8);
            bulk_g2s(stg + s * STAGE_BYTES + 8192, bslab + (size_t)(it + 4) * 8192, 8192, sbase + s * 8);
        }
    }

    __syncthreads();

    // stage per-column correction into smem (past the mbarrier words)
    float* scy = (float*)(smem + 64);
    if (tid < 128) scy[tid] = g_cyf[n0 + tid];
    __syncthreads();

    const int gid = lane >> 2, tig = lane & 3;
#pragma unroll
    for (int mt = 0; mt < 2; mt++) {
#pragma unroll
        for (int h = 0; h < 2; h++) {
            const int rloc = wm * 32 + mt * 16 + h * 8 + gid;
            const float rf = g_rxf[m0 + rloc];
            float* orow = OUT + (size_t)(m0 + rloc) * ND + n0 + wn * 64 + tig * 2;
#pragma unroll
            for (int nt = 0; nt < 8; nt++) {
                const int cidx = wn * 64 + nt * 8 + tig * 2;
                float2 v;
                v.x = SXY * ((float)acc[mt][nt][h * 2 + 0] + rf + scy[cidx + 0]);
                v.y = SXY * ((float)acc[mt][nt][h * 2 + 1] + rf + scy[cidx + 1]);
                *(float2*)(orow + nt * 8) = v;
            }
        }
    }
}

// ------------------------------- launch ------------------------------------

extern "C" void kernel_launch(void* const* d_in, const int* in_sizes, int n_in,
                              void* d_out, int out_size) {
    const int* X32 = (const int*)d_in[0];
    const int* Y32 = (const int*)d_in[1];
    float* OUT = (float*)d_out;

    cudaFuncSetAttribute(gemm_i8_kernel,
                         cudaFuncAttributeMaxDynamicSharedMemorySize, SMEM_TOTAL);

    k_zero_sums<<<16, 256>>>();
    k_pack_x<<<16384, 256>>>((const int4*)X32);
    k_pack_y<<<dim3(ND / 32, KD / 32), 256>>>(Y32);
    k_finalize<<<16, 256>>>();
    gemm_i8_kernel<<<dim3(ND / 128, MD / 128), 256, SMEM_TOTAL>>>(OUT);
}

// round 10
// speedup vs baseline: 2.5741x; 2.5741x over previous
#include <cuda_runtime.h>
#include <cstdint>

// ---------------------------------------------------------------------------
// out = sx*sy * ( X@Y - zpy*rowsum(X)[m] - zpx*colsum(Y)[n] + K*zpx*zpy )
// Inputs are INT32 (harness canonical), values in [-128,127].
// Engine switch: legacy bf16 HMMA (m16n8k16.f32.bf16.bf16.f32).
//   int8 -> bf16 is exact; fp32 accumulation; corrections unchanged.
// Prepass packs PRE-SWIZZLED bf16 slabs (16KB per 128x64 tile):
//   g_xa[mtile][kt], g_yb[ntile][kt]  (Y transposed to [N,K] during pack)
// GEMM: 128x128 CTA tile, K-stage 64, 4-stage cp.async.bulk pipeline,
// 8 warps (4Mx2N), warp tile 32x64, ldmatrix.x4 (proven conventions).
// Launch order: zero, pack_x, pack_y, gemm  -> GEMM is launch #4 (profiled).
// ---------------------------------------------------------------------------

static constexpr int MD = 4096, KD = 4096, ND = 4096;
static constexpr float KZZf = -1843200.0f;     // K*zpx*zpy
static constexpr float SXY  = 0.0215f * 0.0176f;

__device__ uint16_t g_xa[(size_t)MD * KD];     // 32MB bf16 tiled swizzled X
__device__ uint16_t g_yb[(size_t)ND * KD];     // 32MB bf16 tiled swizzled Y^T
__device__ int      g_rxs[MD];                 // rowsum_x (exact int)
__device__ int      g_cys[ND];                 // colsum_y (exact int)

// ------------------------------ helpers -----------------------------------

__device__ __forceinline__ uint32_t smem_u32(const void* p) {
    uint32_t a;
    asm("{ .reg .u64 t; cvta.to.shared.u64 t, %1; cvt.u32.u64 %0, t; }"
        : "=r"(a) : "l"(p));
    return a;
}

#define MBARRIER_INIT(addr, cnt) \
    asm volatile("mbarrier.init.shared.b64 [%0], %1;" :: "r"(addr), "r"(cnt) : "memory")

#define MBARRIER_EXPECT_TX(addr, bytes) \
    asm volatile("mbarrier.arrive.expect_tx.shared.b64 _, [%0], %1;" \
                 :: "r"(addr), "r"(bytes) : "memory")

#define MBARRIER_WAIT_PARITY(addr, ph) do {                                         \
    uint32_t _m = (uint32_t)(addr); uint32_t _p = (uint32_t)(ph); uint32_t _d;      \
    asm volatile("{\n\t.reg .pred p;\n\t"                                           \
        "mbarrier.try_wait.parity.acquire.cta.shared::cta.b64 p, [%1], %2;\n\t"     \
        "selp.b32 %0, 1, 0, p;\n\t}"                                                \
        : "=r"(_d) : "r"(_m), "r"(_p) : "memory");                                  \
    if (!_d) {                                                                      \
        asm volatile("{\n\t.reg .pred P1;\n\t"                                      \
            "WL%=:\n\t"                                                             \
            "mbarrier.try_wait.parity.acquire.cta.shared::cta.b64 P1, [%0], %1, 0x989680;\n\t" \
            "@P1 bra.uni WD%=;\n\t"                                                 \
            "bra.uni WL%=;\n\t"                                                     \
            "WD%=:\n\t}"                                                            \
            :: "r"(_m), "r"(_p) : "memory");                                        \
    } } while (0)

__device__ __forceinline__ void bulk_g2s(uint32_t dst, const void* src,
                                         uint32_t bytes, uint32_t mbar) {
    asm volatile(
        "cp.async.bulk.shared::cluster.global.mbarrier::complete_tx::bytes "
        "[%0], [%1], %2, [%3];"
        :: "r"(dst), "l"(src), "r"(bytes), "r"(mbar) : "memory");
}

#define LDSM4(r0, r1, r2, r3, addr) \
    asm volatile("ldmatrix.sync.aligned.m8n8.x4.shared.b16 {%0,%1,%2,%3}, [%4];" \
                 : "=r"(r0), "=r"(r1), "=r"(r2), "=r"(r3) : "r"(addr))

#define MMA_BF16(d, a0, a1, a2, a3, b0, b1) \
    asm volatile("mma.sync.aligned.m16n8k16.row.col.f32.bf16.bf16.f32 " \
                 "{%0,%1,%2,%3},{%4,%5,%6,%7},{%8,%9},{%0,%1,%2,%3};" \
                 : "+f"((d)[0]), "+f"((d)[1]), "+f"((d)[2]), "+f"((d)[3]) \
                 : "r"(a0), "r"(a1), "r"(a2), "r"(a3), "r"(b0), "r"(b1))

// bf16 slab: 128 rows x 128B (64 bf16). SW128 over 16B slots, slot ^= (r&7).
__device__ __forceinline__ uint32_t soff16(int r, int c16) {
    return (uint32_t)(r * 128 + ((c16 ^ (r & 7)) * 16));
}
// element (row r, k-col kk 0..63), 2B each
__device__ __forceinline__ uint32_t slab_elem(int r, int kk) {
    return soff16(r, kk >> 3) + (kk & 7) * 2;
}

// exact int -> bf16 bits (ints up to 256 have <=8-bit mantissa; truncation exact)
__device__ __forceinline__ uint16_t i2bf(int v) {
    return (uint16_t)(__float_as_uint((float)v) >> 16);
}

// ------------------------------ prepasses ---------------------------------

__global__ void k_zero_sums() {
    int i = blockIdx.x * 256 + threadIdx.x;
    g_rxs[i] = 0;
    g_cys[i] = 0;
}

// X int32 -> bf16 slabs + rowsum
__global__ void k_pack_x(const int4* __restrict__ q) {
    size_t i = (size_t)blockIdx.x * 256 + threadIdx.x;
    int4 v = q[i];
    size_t e = i * 4;
    int m = (int)(e >> 12);
    int k = (int)(e & 4095);
    uint32_t lo = (uint32_t)i2bf(v.x) | ((uint32_t)i2bf(v.y) << 16);
    uint32_t hi = (uint32_t)i2bf(v.z) | ((uint32_t)i2bf(v.w) << 16);
    size_t dst = ((size_t)(m >> 7) * 64 + (k >> 6)) * 16384 + slab_elem(m & 127, k & 63);
    uint2 w; w.x = lo; w.y = hi;
    *(uint2*)((char*)g_xa + dst) = w;

    int part = v.x + v.y + v.z + v.w;
#pragma unroll
    for (int s = 16; s; s >>= 1) part += __shfl_xor_sync(0xffffffffu, part, s);
    if ((threadIdx.x & 31) == 0) atomicAdd(&g_rxs[m], part);   // warp spans one row
}

// Y int32 [K,N] -> bf16 transposed slabs + colsum
__global__ void k_pack_y(const int* __restrict__ Y) {
    __shared__ int8_t tile[32][36];
    int n0 = blockIdx.x * 32, k0 = blockIdx.y * 32;
    int t = threadIdx.x;
    {
        int k = t >> 3, nq = (t & 7) * 4;
        int4 v = *(const int4*)(Y + (size_t)(k0 + k) * ND + n0 + nq);
        tile[nq + 0][k] = (int8_t)v.x;
        tile[nq + 1][k] = (int8_t)v.y;
        tile[nq + 2][k] = (int8_t)v.z;
        tile[nq + 3][k] = (int8_t)v.w;
    }
    __syncthreads();
    {
        int nl = t >> 3, kq = (t & 7) * 4;
        int e0 = tile[nl][kq + 0], e1 = tile[nl][kq + 1];
        int e2 = tile[nl][kq + 2], e3 = tile[nl][kq + 3];
        int n = n0 + nl, k = k0 + kq;
        uint32_t lo = (uint32_t)i2bf(e0) | ((uint32_t)i2bf(e1) << 16);
        uint32_t hi = (uint32_t)i2bf(e2) | ((uint32_t)i2bf(e3) << 16);
        size_t dst = ((size_t)(n >> 7) * 64 + (k >> 6)) * 16384 + slab_elem(n & 127, k & 63);
        uint2 w; w.x = lo; w.y = hi;
        *(uint2*)((char*)g_yb + dst) = w;

        int part = e0 + e1 + e2 + e3;
        part += __shfl_xor_sync(0xffffffffu, part, 1);
        part += __shfl_xor_sync(0xffffffffu, part, 2);
        part += __shfl_xor_sync(0xffffffffu, part, 4);
        if ((t & 7) == 0) atomicAdd(&g_cys[n], part);
    }
}

// ------------------------------- GEMM -------------------------------------
// Stage = A(16KB) + B(16KB) = 32KB; 4 stages (128KB) + 1KB header.

static constexpr int STAGES = 4;
static constexpr int STAGE_BYTES = 32768;
static constexpr int STAGE0_OFF = 1024;
static constexpr int SMEM_TOTAL = STAGE0_OFF + STAGES * STAGE_BYTES;  // 132096
static constexpr int KITERS = KD / 64;                                // 64

__global__ void __launch_bounds__(256)
gemm_bf16_kernel(float* __restrict__ OUT) {
    extern __shared__ char smem[];
    const uint32_t sbase = smem_u32(smem);
    const uint32_t stg = sbase + STAGE0_OFF;
    const int tid = threadIdx.x;
    const int lane = tid & 31;
    const int wid = tid >> 5;
    const int wm = wid & 3;                 // M quadrant (32 rows)
    const int wn = wid >> 2;                // N half (64 cols)
    const int m0 = blockIdx.y * 128;
    const int n0 = blockIdx.x * 128;

    const int sel = lane >> 3;              // ldmatrix matrix id
    const int l7  = lane & 7;

    const char* aslab = (const char*)g_xa + (size_t)(m0 >> 7) * 64 * 16384;
    const char* bslab = (const char*)g_yb + (size_t)(n0 >> 7) * 64 * 16384;

    if (tid == 0) {
#pragma unroll
        for (int s = 0; s < STAGES; s++) MBARRIER_INIT(sbase + s * 8, 1);
        asm volatile("fence.proxy.async.shared::cta;" ::: "memory");
    }
    __syncthreads();

    if (tid == 0) {
#pragma unroll
        for (int p = 0; p < STAGES; p++) {
            MBARRIER_EXPECT_TX(sbase + p * 8, STAGE_BYTES);
            bulk_g2s(stg + p * STAGE_BYTES,         aslab + (size_t)p * 16384, 16384, sbase + p * 8);
            bulk_g2s(stg + p * STAGE_BYTES + 16384, bslab + (size_t)p * 16384, 16384, sbase + p * 8);
        }
    }

    float acc[2][8][4];
#pragma unroll
    for (int i = 0; i < 2; i++)
#pragma unroll
        for (int j = 0; j < 8; j++)
#pragma unroll
            for (int q = 0; q < 4; q++) acc[i][j][q] = 0.0f;

    for (int it = 0; it < KITERS; it++) {
        const int s = it & 3;
        MBARRIER_WAIT_PARITY(sbase + s * 8, (it >> 2) & 1);

        const uint32_t sA = stg + s * STAGE_BYTES;
        const uint32_t sB = sA + 16384;

#pragma unroll
        for (int kq = 0; kq < 4; kq++) {          // 4 x k16 per stage
            // A: 2 LDSM4 (rows 32, k16): matrices (rowhalf=sel&1, kchunk=sel>>1)
            uint32_t a[2][4];
#pragma unroll
            for (int mt = 0; mt < 2; mt++) {
                int row = wm * 32 + mt * 16 + l7 + (sel & 1) * 8;
                int c16 = kq * 2 + (sel >> 1);
                LDSM4(a[mt][0], a[mt][1], a[mt][2], a[mt][3], sA + soff16(row, c16));
            }
            // B: 4 LDSM4 (n 64, k16): matrices (nhalf=sel>>1, kchunk=sel&1)
            uint32_t b[4][4];
#pragma unroll
            for (int np = 0; np < 4; np++) {
                int row = wn * 64 + np * 16 + (sel >> 1) * 8 + l7;
                int c16 = kq * 2 + (sel & 1);
                LDSM4(b[np][0], b[np][1], b[np][2], b[np][3], sB + soff16(row, c16));
            }
            // 16 HMMA
#pragma unroll
            for (int np = 0; np < 4; np++) {
                MMA_BF16(acc[0][np * 2 + 0], a[0][0], a[0][1], a[0][2], a[0][3],
                         b[np][0], b[np][1]);
                MMA_BF16(acc[0][np * 2 + 1], a[0][0], a[0][1], a[0][2], a[0][3],
                         b[np][2], b[np][3]);
                MMA_BF16(acc[1][np * 2 + 0], a[1][0], a[1][1], a[1][2], a[1][3],
                         b[np][0], b[np][1]);
                MMA_BF16(acc[1][np * 2 + 1], a[1][0], a[1][1], a[1][2], a[1][3],
                         b[np][2], b[np][3]);
            }
        }

        __syncthreads();                       // all warps done with stage s
        if (tid == 0 && it + 4 < KITERS) {
            MBARRIER_EXPECT_TX(sbase + s * 8, STAGE_BYTES);
            bulk_g2s(stg + s * STAGE_BYTES,         aslab + (size_t)(it + 4) * 16384, 16384, sbase + s * 8);
            bulk_g2s(stg + s * STAGE_BYTES + 16384, bslab + (size_t)(it + 4) * 16384, 16384, sbase + s * 8);
        }
    }

    __syncthreads();

    // per-column correction (finalize folded in): scy = 25*colsum + KZZ
    float* scy = (float*)(smem + 64);
    if (tid < 128) scy[tid] = 25.0f * (float)g_cys[n0 + tid] + KZZf;
    __syncthreads();

    const int gid = lane >> 2, tig = lane & 3;
#pragma unroll
    for (int mt = 0; mt < 2; mt++) {
#pragma unroll
        for (int h = 0; h < 2; h++) {
            const int rloc = wm * 32 + mt * 16 + h * 8 + gid;
            const float rf = -18.0f * (float)g_rxs[m0 + rloc];
            float* orow = OUT + (size_t)(m0 + rloc) * ND + n0 + wn * 64 + tig * 2;
#pragma unroll
            for (int nt = 0; nt < 8; nt++) {
                const int cidx = wn * 64 + nt * 8 + tig * 2;
                float2 v;
                v.x = SXY * (acc[mt][nt][h * 2 + 0] + rf + scy[cidx + 0]);
                v.y = SXY * (acc[mt][nt][h * 2 + 1] + rf + scy[cidx + 1]);
                *(float2*)(orow + nt * 8) = v;
            }
        }
    }
}

// ------------------------------- launch ------------------------------------

extern "C" void kernel_launch(void* const* d_in, const int* in_sizes, int n_in,
                              void* d_out, int out_size) {
    const int* X32 = (const int*)d_in[0];
    const int* Y32 = (const int*)d_in[1];
    float* OUT = (float*)d_out;

    cudaFuncSetAttribute(gemm_bf16_kernel,
                         cudaFuncAttributeMaxDynamicSharedMemorySize, SMEM_TOTAL);

    k_zero_sums<<<16, 256>>>();
    k_pack_x<<<16384, 256>>>((const int4*)X32);
    k_pack_y<<<dim3(ND / 32, KD / 32), 256>>>(Y32);
    gemm_bf16_kernel<<<dim3(ND / 128, MD / 128), 256, SMEM_TOTAL>>>(OUT);  // launch #4 -> profiled
}

// round 11
// speedup vs baseline: 2.9498x; 1.1459x over previous
#include <cuda_runtime.h>
#include <cstdint>

// ---------------------------------------------------------------------------
// out = sx*sy * ( X@Y - zpy*rowsum(X)[m] - zpx*colsum(Y)[n] + K*zpx*zpy )
// Inputs are INT32 (harness canonical), values in [-128,127].
// Engine: legacy bf16 HMMA (m16n8k16.f32.bf16.bf16.f32); int8->bf16 exact.
// Prepass packs PRE-SWIZZLED bf16 slabs (16KB per 128x64 tile).
// GEMM: 128x128 CTA tile, K-stage 64, 3-stage cp.async.bulk pipeline,
// 2 CTAs/SM (97KB smem each) to fill stage-barrier gaps.
// ---------------------------------------------------------------------------

static constexpr int MD = 4096, KD = 4096, ND = 4096;
static constexpr float KZZf = -1843200.0f;     // K*zpx*zpy
static constexpr float SXY  = 0.0215f * 0.0176f;

__device__ uint16_t g_xa[(size_t)MD * KD];     // 32MB bf16 tiled swizzled X
__device__ uint16_t g_yb[(size_t)ND * KD];     // 32MB bf16 tiled swizzled Y^T
__device__ int      g_rxs[MD];                 // rowsum_x (exact int)
__device__ int      g_cys[ND];                 // colsum_y (exact int)

// ------------------------------ helpers -----------------------------------

__device__ __forceinline__ uint32_t smem_u32(const void* p) {
    uint32_t a;
    asm("{ .reg .u64 t; cvta.to.shared.u64 t, %1; cvt.u32.u64 %0, t; }"
        : "=r"(a) : "l"(p));
    return a;
}

#define MBARRIER_INIT(addr, cnt) \
    asm volatile("mbarrier.init.shared.b64 [%0], %1;" :: "r"(addr), "r"(cnt) : "memory")

#define MBARRIER_EXPECT_TX(addr, bytes) \
    asm volatile("mbarrier.arrive.expect_tx.shared.b64 _, [%0], %1;" \
                 :: "r"(addr), "r"(bytes) : "memory")

#define MBARRIER_WAIT_PARITY(addr, ph) do {                                         \
    uint32_t _m = (uint32_t)(addr); uint32_t _p = (uint32_t)(ph); uint32_t _d;      \
    asm volatile("{\n\t.reg .pred p;\n\t"                                           \
        "mbarrier.try_wait.parity.acquire.cta.shared::cta.b64 p, [%1], %2;\n\t"     \
        "selp.b32 %0, 1, 0, p;\n\t}"                                                \
        : "=r"(_d) : "r"(_m), "r"(_p) : "memory");                                  \
    if (!_d) {                                                                      \
        asm volatile("{\n\t.reg .pred P1;\n\t"                                      \
            "WL%=:\n\t"                                                             \
            "mbarrier.try_wait.parity.acquire.cta.shared::cta.b64 P1, [%0], %1, 0x989680;\n\t" \
            "@P1 bra.uni WD%=;\n\t"                                                 \
            "bra.uni WL%=;\n\t"                                                     \
            "WD%=:\n\t}"                                                            \
            :: "r"(_m), "r"(_p) : "memory");                                        \
    } } while (0)

__device__ __forceinline__ void bulk_g2s(uint32_t dst, const void* src,
                                         uint32_t bytes, uint32_t mbar) {
    asm volatile(
        "cp.async.bulk.shared::cluster.global.mbarrier::complete_tx::bytes "
        "[%0], [%1], %2, [%3];"
        :: "r"(dst), "l"(src), "r"(bytes), "r"(mbar) : "memory");
}

#define LDSM4(r0, r1, r2, r3, addr) \
    asm volatile("ldmatrix.sync.aligned.m8n8.x4.shared.b16 {%0,%1,%2,%3}, [%4];" \
                 : "=r"(r0), "=r"(r1), "=r"(r2), "=r"(r3) : "r"(addr))

#define MMA_BF16(d, a0, a1, a2, a3, b0, b1) \
    asm volatile("mma.sync.aligned.m16n8k16.row.col.f32.bf16.bf16.f32 " \
                 "{%0,%1,%2,%3},{%4,%5,%6,%7},{%8,%9},{%0,%1,%2,%3};" \
                 : "+f"((d)[0]), "+f"((d)[1]), "+f"((d)[2]), "+f"((d)[3]) \
                 : "r"(a0), "r"(a1), "r"(a2), "r"(a3), "r"(b0), "r"(b1))

// bf16 slab: 128 rows x 128B (64 bf16). SW128 over 16B slots, slot ^= (r&7).
__device__ __forceinline__ uint32_t soff16(int r, int c16) {
    return (uint32_t)(r * 128 + ((c16 ^ (r & 7)) * 16));
}
__device__ __forceinline__ uint32_t slab_elem(int r, int kk) {
    return soff16(r, kk >> 3) + (kk & 7) * 2;
}

// exact int -> bf16 bits
__device__ __forceinline__ uint16_t i2bf(int v) {
    return (uint16_t)(__float_as_uint((float)v) >> 16);
}

// ------------------------------ prepasses ---------------------------------

__global__ void k_zero_sums() {
    int i = blockIdx.x * 256 + threadIdx.x;
    g_rxs[i] = 0;
    g_cys[i] = 0;
}

__global__ void k_pack_x(const int4* __restrict__ q) {
    size_t i = (size_t)blockIdx.x * 256 + threadIdx.x;
    int4 v = q[i];
    size_t e = i * 4;
    int m = (int)(e >> 12);
    int k = (int)(e & 4095);
    uint32_t lo = (uint32_t)i2bf(v.x) | ((uint32_t)i2bf(v.y) << 16);
    uint32_t hi = (uint32_t)i2bf(v.z) | ((uint32_t)i2bf(v.w) << 16);
    size_t dst = ((size_t)(m >> 7) * 64 + (k >> 6)) * 16384 + slab_elem(m & 127, k & 63);
    uint2 w; w.x = lo; w.y = hi;
    *(uint2*)((char*)g_xa + dst) = w;

    int part = v.x + v.y + v.z + v.w;
#pragma unroll
    for (int s = 16; s; s >>= 1) part += __shfl_xor_sync(0xffffffffu, part, s);
    if ((threadIdx.x & 31) == 0) atomicAdd(&g_rxs[m], part);
}

__global__ void k_pack_y(const int* __restrict__ Y) {
    __shared__ int8_t tile[32][36];
    int n0 = blockIdx.x * 32, k0 = blockIdx.y * 32;
    int t = threadIdx.x;
    {
        int k = t >> 3, nq = (t & 7) * 4;
        int4 v = *(const int4*)(Y + (size_t)(k0 + k) * ND + n0 + nq);
        tile[nq + 0][k] = (int8_t)v.x;
        tile[nq + 1][k] = (int8_t)v.y;
        tile[nq + 2][k] = (int8_t)v.z;
        tile[nq + 3][k] = (int8_t)v.w;
    }
    __syncthreads();
    {
        int nl = t >> 3, kq = (t & 7) * 4;
        int e0 = tile[nl][kq + 0], e1 = tile[nl][kq + 1];
        int e2 = tile[nl][kq + 2], e3 = tile[nl][kq + 3];
        int n = n0 + nl, k = k0 + kq;
        uint32_t lo = (uint32_t)i2bf(e0) | ((uint32_t)i2bf(e1) << 16);
        uint32_t hi = (uint32_t)i2bf(e2) | ((uint32_t)i2bf(e3) << 16);
        size_t dst = ((size_t)(n >> 7) * 64 + (k >> 6)) * 16384 + slab_elem(n & 127, k & 63);
        uint2 w; w.x = lo; w.y = hi;
        *(uint2*)((char*)g_yb + dst) = w;

        int part = e0 + e1 + e2 + e3;
        part += __shfl_xor_sync(0xffffffffu, part, 1);
        part += __shfl_xor_sync(0xffffffffu, part, 2);
        part += __shfl_xor_sync(0xffffffffu, part, 4);
        if ((t & 7) == 0) atomicAdd(&g_cys[n], part);
    }
}

// ------------------------------- GEMM -------------------------------------
// Stage = A(16KB) + B(16KB) = 32KB; 3 stages (96KB) + 1KB header = 97KB.
// 2 CTAs/SM.

static constexpr int STAGES = 3;
static constexpr int STAGE_BYTES = 32768;
static constexpr int STAGE0_OFF = 1024;
static constexpr int SMEM_TOTAL = STAGE0_OFF + STAGES * STAGE_BYTES;  // 99328
static constexpr int KITERS = KD / 64;                                // 64

__global__ void __launch_bounds__(256, 2)
gemm_bf16_kernel(float* __restrict__ OUT) {
    extern __shared__ char smem[];
    const uint32_t sbase = smem_u32(smem);
    const uint32_t stg = sbase + STAGE0_OFF;
    const int tid = threadIdx.x;
    const int lane = tid & 31;
    const int wid = tid >> 5;
    const int wm = wid & 3;                 // M quadrant (32 rows)
    const int wn = wid >> 2;                // N half (64 cols)
    const int m0 = blockIdx.y * 128;
    const int n0 = blockIdx.x * 128;

    const int sel = lane >> 3;              // ldmatrix matrix id
    const int l7  = lane & 7;

    const char* aslab = (const char*)g_xa + (size_t)(m0 >> 7) * 64 * 16384;
    const char* bslab = (const char*)g_yb + (size_t)(n0 >> 7) * 64 * 16384;

    if (tid == 0) {
#pragma unroll
        for (int s = 0; s < STAGES; s++) MBARRIER_INIT(sbase + s * 8, 1);
        asm volatile("fence.proxy.async.shared::cta;" ::: "memory");
    }
    __syncthreads();

    if (tid == 0) {
#pragma unroll
        for (int p = 0; p < STAGES; p++) {
            MBARRIER_EXPECT_TX(sbase + p * 8, STAGE_BYTES);
            bulk_g2s(stg + p * STAGE_BYTES,         aslab + (size_t)p * 16384, 16384, sbase + p * 8);
            bulk_g2s(stg + p * STAGE_BYTES + 16384, bslab + (size_t)p * 16384, 16384, sbase + p * 8);
        }
    }

    float acc[2][8][4];
#pragma unroll
    for (int i = 0; i < 2; i++)
#pragma unroll
        for (int j = 0; j < 8; j++)
#pragma unroll
            for (int q = 0; q < 4; q++) acc[i][j][q] = 0.0f;

    int s = 0, ph = 0;                      // stage index / full-barrier parity
    for (int it = 0; it < KITERS; it++) {
        MBARRIER_WAIT_PARITY(sbase + s * 8, ph);

        const uint32_t sA = stg + s * STAGE_BYTES;
        const uint32_t sB = sA + 16384;

#pragma unroll
        for (int kq = 0; kq < 4; kq++) {          // 4 x k16 per stage
            uint32_t a[2][4];
#pragma unroll
            for (int mt = 0; mt < 2; mt++) {
                int row = wm * 32 + mt * 16 + l7 + (sel & 1) * 8;
                int c16 = kq * 2 + (sel >> 1);
                LDSM4(a[mt][0], a[mt][1], a[mt][2], a[mt][3], sA + soff16(row, c16));
            }
            uint32_t b[4][4];
#pragma unroll
            for (int np = 0; np < 4; np++) {
                int row = wn * 64 + np * 16 + (sel >> 1) * 8 + l7;
                int c16 = kq * 2 + (sel & 1);
                LDSM4(b[np][0], b[np][1], b[np][2], b[np][3], sB + soff16(row, c16));
            }
#pragma unroll
            for (int np = 0; np < 4; np++) {
                MMA_BF16(acc[0][np * 2 + 0], a[0][0], a[0][1], a[0][2], a[0][3],
                         b[np][0], b[np][1]);
                MMA_BF16(acc[0][np * 2 + 1], a[0][0], a[0][1], a[0][2], a[0][3],
                         b[np][2], b[np][3]);
                MMA_BF16(acc[1][np * 2 + 0], a[1][0], a[1][1], a[1][2], a[1][3],
                         b[np][0], b[np][1]);
                MMA_BF16(acc[1][np * 2 + 1], a[1][0], a[1][1], a[1][2], a[1][3],
                         b[np][2], b[np][3]);
            }
        }

        __syncthreads();                       // all warps done with stage s
        if (tid == 0 && it + STAGES < KITERS) {
            MBARRIER_EXPECT_TX(sbase + s * 8, STAGE_BYTES);
            bulk_g2s(stg + s * STAGE_BYTES,         aslab + (size_t)(it + STAGES) * 16384, 16384, sbase + s * 8);
            bulk_g2s(stg + s * STAGE_BYTES + 16384, bslab + (size_t)(it + STAGES) * 16384, 16384, sbase + s * 8);
        }
        if (++s == STAGES) { s = 0; ph ^= 1; }
    }

    __syncthreads();

    // per-column correction: scy = 25*colsum + KZZ
    float* scy = (float*)(smem + 64);
    if (tid < 128) scy[tid] = 25.0f * (float)g_cys[n0 + tid] + KZZf;
    __syncthreads();

    const int gid = lane >> 2, tig = lane & 3;
#pragma unroll
    for (int mt = 0; mt < 2; mt++) {
#pragma unroll
        for (int h = 0; h < 2; h++) {
            const int rloc = wm * 32 + mt * 16 + h * 8 + gid;
            const float rf = -18.0f * (float)g_rxs[m0 + rloc];
            float* orow = OUT + (size_t)(m0 + rloc) * ND + n0 + wn * 64 + tig * 2;
#pragma unroll
            for (int nt = 0; nt < 8; nt++) {
                const int cidx = wn * 64 + nt * 8 + tig * 2;
                float2 v;
                v.x = SXY * (acc[mt][nt][h * 2 + 0] + rf + scy[cidx + 0]);
                v.y = SXY * (acc[mt][nt][h * 2 + 1] + rf + scy[cidx + 1]);
                *(float2*)(orow + nt * 8) = v;
            }
        }
    }
}

// ------------------------------- launch ------------------------------------

extern "C" void kernel_launch(void* const* d_in, const int* in_sizes, int n_in,
                              void* d_out, int out_size) {
    const int* X32 = (const int*)d_in[0];
    const int* Y32 = (const int*)d_in[1];
    float* OUT = (float*)d_out;

    cudaFuncSetAttribute(gemm_bf16_kernel,
                         cudaFuncAttributeMaxDynamicSharedMemorySize, SMEM_TOTAL);

    k_zero_sums<<<16, 256>>>();
    k_pack_x<<<16384, 256>>>((const int4*)X32);
    k_pack_y<<<dim3(ND / 32, KD / 32), 256>>>(Y32);
    gemm_bf16_kernel<<<dim3(ND / 128, MD / 128), 256, SMEM_TOTAL>>>(OUT);  // launch #4 -> profiled
}

// round 12
// speedup vs baseline: 3.1281x; 1.0604x over previous
#include <cuda_runtime.h>
#include <cstdint>

// ---------------------------------------------------------------------------
// out = sx*sy * ( X@Y - zpy*rowsum(X)[m] - zpx*colsum(Y)[n] + K*zpx*zpy )
// Inputs are INT32 (harness canonical), values in [-128,127].
// Engine: legacy bf16 HMMA (m16n8k16.f32.bf16.bf16.f32); int8->bf16 exact.
// Prepass packs PRE-SWIZZLED bf16 slabs (16KB per 128x64 tile).
// GEMM: 128x128 CTA tile, K-stage 64, 3-stage cp.async.bulk pipeline,
// 2 CTAs/SM; warp-decoupled stage release via empty-mbarriers (no
// per-iteration __syncthreads).
// ---------------------------------------------------------------------------

static constexpr int MD = 4096, KD = 4096, ND = 4096;
static constexpr float KZZf = -1843200.0f;     // K*zpx*zpy
static constexpr float SXY  = 0.0215f * 0.0176f;

__device__ uint16_t g_xa[(size_t)MD * KD];     // 32MB bf16 tiled swizzled X
__device__ uint16_t g_yb[(size_t)ND * KD];     // 32MB bf16 tiled swizzled Y^T
__device__ int      g_rxs[MD];                 // rowsum_x (exact int)
__device__ int      g_cys[ND];                 // colsum_y (exact int)

// ------------------------------ helpers -----------------------------------

__device__ __forceinline__ uint32_t smem_u32(const void* p) {
    uint32_t a;
    asm("{ .reg .u64 t; cvta.to.shared.u64 t, %1; cvt.u32.u64 %0, t; }"
        : "=r"(a) : "l"(p));
    return a;
}

#define MBARRIER_INIT(addr, cnt) \
    asm volatile("mbarrier.init.shared.b64 [%0], %1;" :: "r"(addr), "r"(cnt) : "memory")

#define MBARRIER_ARRIVE(addr) \
    asm volatile("mbarrier.arrive.shared.b64 _, [%0];" :: "r"(addr) : "memory")

#define MBARRIER_EXPECT_TX(addr, bytes) \
    asm volatile("mbarrier.arrive.expect_tx.shared.b64 _, [%0], %1;" \
                 :: "r"(addr), "r"(bytes) : "memory")

#define MBARRIER_WAIT_PARITY(addr, ph) do {                                         \
    uint32_t _m = (uint32_t)(addr); uint32_t _p = (uint32_t)(ph); uint32_t _d;      \
    asm volatile("{\n\t.reg .pred p;\n\t"                                           \
        "mbarrier.try_wait.parity.acquire.cta.shared::cta.b64 p, [%1], %2;\n\t"     \
        "selp.b32 %0, 1, 0, p;\n\t}"                                                \
        : "=r"(_d) : "r"(_m), "r"(_p) : "memory");                                  \
    if (!_d) {                                                                      \
        asm volatile("{\n\t.reg .pred P1;\n\t"                                      \
            "WL%=:\n\t"                                                             \
            "mbarrier.try_wait.parity.acquire.cta.shared::cta.b64 P1, [%0], %1, 0x989680;\n\t" \
            "@P1 bra.uni WD%=;\n\t"                                                 \
            "bra.uni WL%=;\n\t"                                                     \
            "WD%=:\n\t}"                                                            \
            :: "r"(_m), "r"(_p) : "memory");                                        \
    } } while (0)

__device__ __forceinline__ void bulk_g2s(uint32_t dst, const void* src,
                                         uint32_t bytes, uint32_t mbar) {
    asm volatile(
        "cp.async.bulk.shared::cluster.global.mbarrier::complete_tx::bytes "
        "[%0], [%1], %2, [%3];"
        :: "r"(dst), "l"(src), "r"(bytes), "r"(mbar) : "memory");
}

#define LDSM4(r0, r1, r2, r3, addr) \
    asm volatile("ldmatrix.sync.aligned.m8n8.x4.shared.b16 {%0,%1,%2,%3}, [%4];" \
                 : "=r"(r0), "=r"(r1), "=r"(r2), "=r"(r3) : "r"(addr))

#define MMA_BF16(d, a0, a1, a2, a3, b0, b1) \
    asm volatile("mma.sync.aligned.m16n8k16.row.col.f32.bf16.bf16.f32 " \
                 "{%0,%1,%2,%3},{%4,%5,%6,%7},{%8,%9},{%0,%1,%2,%3};" \
                 : "+f"((d)[0]), "+f"((d)[1]), "+f"((d)[2]), "+f"((d)[3]) \
                 : "r"(a0), "r"(a1), "r"(a2), "r"(a3), "r"(b0), "r"(b1))

// bf16 slab: 128 rows x 128B (64 bf16). SW128 over 16B slots, slot ^= (r&7).
__device__ __forceinline__ uint32_t soff16(int r, int c16) {
    return (uint32_t)(r * 128 + ((c16 ^ (r & 7)) * 16));
}
__device__ __forceinline__ uint32_t slab_elem(int r, int kk) {
    return soff16(r, kk >> 3) + (kk & 7) * 2;
}

// exact int -> bf16 bits
__device__ __forceinline__ uint16_t i2bf(int v) {
    return (uint16_t)(__float_as_uint((float)v) >> 16);
}

// ------------------------------ prepasses ---------------------------------

__global__ void k_zero_sums() {
    int i = blockIdx.x * 256 + threadIdx.x;
    g_rxs[i] = 0;
    g_cys[i] = 0;
}

// merged pack: blocks [0,16384) pack X; blocks [16384,32768) pack+transpose Y
__global__ void k_pack_xy(const int4* __restrict__ qx, const int* __restrict__ Y) {
    if (blockIdx.x < 16384) {
        size_t i = (size_t)blockIdx.x * 256 + threadIdx.x;
        int4 v = qx[i];
        size_t e = i * 4;
        int m = (int)(e >> 12);
        int k = (int)(e & 4095);
        uint32_t lo = (uint32_t)i2bf(v.x) | ((uint32_t)i2bf(v.y) << 16);
        uint32_t hi = (uint32_t)i2bf(v.z) | ((uint32_t)i2bf(v.w) << 16);
        size_t dst = ((size_t)(m >> 7) * 64 + (k >> 6)) * 16384 + slab_elem(m & 127, k & 63);
        uint2 w; w.x = lo; w.y = hi;
        *(uint2*)((char*)g_xa + dst) = w;

        int part = v.x + v.y + v.z + v.w;
#pragma unroll
        for (int s = 16; s; s >>= 1) part += __shfl_xor_sync(0xffffffffu, part, s);
        if ((threadIdx.x & 31) == 0) atomicAdd(&g_rxs[m], part);
    } else {
        __shared__ int8_t tile[32][36];
        int bx = blockIdx.x - 16384;
        int n0 = (bx & 127) * 32, k0 = (bx >> 7) * 32;
        int t = threadIdx.x;
        {
            int k = t >> 3, nq = (t & 7) * 4;
            int4 v = *(const int4*)(Y + (size_t)(k0 + k) * ND + n0 + nq);
            tile[nq + 0][k] = (int8_t)v.x;
            tile[nq + 1][k] = (int8_t)v.y;
            tile[nq + 2][k] = (int8_t)v.z;
            tile[nq + 3][k] = (int8_t)v.w;
        }
        __syncthreads();
        {
            int nl = t >> 3, kq = (t & 7) * 4;
            int e0 = tile[nl][kq + 0], e1 = tile[nl][kq + 1];
            int e2 = tile[nl][kq + 2], e3 = tile[nl][kq + 3];
            int n = n0 + nl, k = k0 + kq;
            uint32_t lo = (uint32_t)i2bf(e0) | ((uint32_t)i2bf(e1) << 16);
            uint32_t hi = (uint32_t)i2bf(e2) | ((uint32_t)i2bf(e3) << 16);
            size_t dst = ((size_t)(n >> 7) * 64 + (k >> 6)) * 16384 + slab_elem(n & 127, k & 63);
            uint2 w; w.x = lo; w.y = hi;
            *(uint2*)((char*)g_yb + dst) = w;

            int part = e0 + e1 + e2 + e3;
            part += __shfl_xor_sync(0xffffffffu, part, 1);
            part += __shfl_xor_sync(0xffffffffu, part, 2);
            part += __shfl_xor_sync(0xffffffffu, part, 4);
            if ((t & 7) == 0) atomicAdd(&g_cys[n], part);
        }
    }
}

// ------------------------------- GEMM -------------------------------------
// Stage = A(16KB) + B(16KB) = 32KB; 3 stages (96KB) + 1KB header = 97KB.
// 2 CTAs/SM. full[s] at +s*8, empty[s] at +32+s*8 (count 8), scy at +64.

static constexpr int STAGES = 3;
static constexpr int STAGE_BYTES = 32768;
static constexpr int STAGE0_OFF = 1024;
static constexpr int SMEM_TOTAL = STAGE0_OFF + STAGES * STAGE_BYTES;  // 99328
static constexpr int KITERS = KD / 64;                                // 64

__global__ void __launch_bounds__(256, 2)
gemm_bf16_kernel(float* __restrict__ OUT) {
    extern __shared__ char smem[];
    const uint32_t sbase = smem_u32(smem);
    const uint32_t stg = sbase + STAGE0_OFF;
    const int tid = threadIdx.x;
    const int lane = tid & 31;
    const int wid = tid >> 5;
    const int wm = wid & 3;                 // M quadrant (32 rows)
    const int wn = wid >> 2;                // N half (64 cols)
    const int m0 = blockIdx.y * 128;
    const int n0 = blockIdx.x * 128;

    const int sel = lane >> 3;              // ldmatrix matrix id
    const int l7  = lane & 7;

    const char* aslab = (const char*)g_xa + (size_t)(m0 >> 7) * 64 * 16384;
    const char* bslab = (const char*)g_yb + (size_t)(n0 >> 7) * 64 * 16384;

    if (tid == 0) {
#pragma unroll
        for (int s = 0; s < STAGES; s++) {
            MBARRIER_INIT(sbase + s * 8, 1);            // full: tx-based
            MBARRIER_INIT(sbase + 32 + s * 8, 8);       // empty: 8 warps
        }
        asm volatile("fence.proxy.async.shared::cta;" ::: "memory");
    }
    __syncthreads();

    if (tid == 0) {
#pragma unroll
        for (int p = 0; p < STAGES; p++) {
            MBARRIER_EXPECT_TX(sbase + p * 8, STAGE_BYTES);
            bulk_g2s(stg + p * STAGE_BYTES,         aslab + (size_t)p * 16384, 16384, sbase + p * 8);
            bulk_g2s(stg + p * STAGE_BYTES + 16384, bslab + (size_t)p * 16384, 16384, sbase + p * 8);
        }
    }

    float acc[2][8][4];
#pragma unroll
    for (int i = 0; i < 2; i++)
#pragma unroll
        for (int j = 0; j < 8; j++)
#pragma unroll
            for (int q = 0; q < 4; q++) acc[i][j][q] = 0.0f;

    int s = 0, ph = 0;
    for (int it = 0; it < KITERS; it++) {
        MBARRIER_WAIT_PARITY(sbase + s * 8, ph);        // full[s]

        const uint32_t sA = stg + s * STAGE_BYTES;
        const uint32_t sB = sA + 16384;

#pragma unroll
        for (int kq = 0; kq < 4; kq++) {          // 4 x k16 per stage
            uint32_t a[2][4];
#pragma unroll
            for (int mt = 0; mt < 2; mt++) {
                int row = wm * 32 + mt * 16 + l7 + (sel & 1) * 8;
                int c16 = kq * 2 + (sel >> 1);
                LDSM4(a[mt][0], a[mt][1], a[mt][2], a[mt][3], sA + soff16(row, c16));
            }
            uint32_t b[4][4];
#pragma unroll
            for (int np = 0; np < 4; np++) {
                int row = wn * 64 + np * 16 + (sel >> 1) * 8 + l7;
                int c16 = kq * 2 + (sel & 1);
                LDSM4(b[np][0], b[np][1], b[np][2], b[np][3], sB + soff16(row, c16));
            }
#pragma unroll
            for (int np = 0; np < 4; np++) {
                MMA_BF16(acc[0][np * 2 + 0], a[0][0], a[0][1], a[0][2], a[0][3],
                         b[np][0], b[np][1]);
                MMA_BF16(acc[0][np * 2 + 1], a[0][0], a[0][1], a[0][2], a[0][3],
                         b[np][2], b[np][3]);
                MMA_BF16(acc[1][np * 2 + 0], a[1][0], a[1][1], a[1][2], a[1][3],
                         b[np][0], b[np][1]);
                MMA_BF16(acc[1][np * 2 + 1], a[1][0], a[1][1], a[1][2], a[1][3],
                         b[np][2], b[np][3]);
            }
        }

        // warp done reading stage s -> release it (no CTA-wide sync)
        if (lane == 0) MBARRIER_ARRIVE(sbase + 32 + s * 8);

        // producer refill: wait all 8 warps released, then bulk-copy next tile
        if (tid == 0 && it + STAGES < KITERS) {
            MBARRIER_WAIT_PARITY(sbase + 32 + s * 8, ph);   // empty[s]
            MBARRIER_EXPECT_TX(sbase + s * 8, STAGE_BYTES);
            bulk_g2s(stg + s * STAGE_BYTES,         aslab + (size_t)(it + STAGES) * 16384, 16384, sbase + s * 8);
            bulk_g2s(stg + s * STAGE_BYTES + 16384, bslab + (size_t)(it + STAGES) * 16384, 16384, sbase + s * 8);
        }
        if (++s == STAGES) { s = 0; ph ^= 1; }
    }

    __syncthreads();

    // per-column correction: scy = 25*colsum + KZZ
    float* scy = (float*)(smem + 64);
    if (tid < 128) scy[tid] = 25.0f * (float)g_cys[n0 + tid] + KZZf;
    __syncthreads();

    const int gid = lane >> 2, tig = lane & 3;
#pragma unroll
    for (int mt = 0; mt < 2; mt++) {
#pragma unroll
        for (int h = 0; h < 2; h++) {
            const int rloc = wm * 32 + mt * 16 + h * 8 + gid;
            const float rf = -18.0f * (float)g_rxs[m0 + rloc];
            float* orow = OUT + (size_t)(m0 + rloc) * ND + n0 + wn * 64 + tig * 2;
#pragma unroll
            for (int nt = 0; nt < 8; nt++) {
                const int cidx = wn * 64 + nt * 8 + tig * 2;
                float2 v;
                v.x = SXY * (acc[mt][nt][h * 2 + 0] + rf + scy[cidx + 0]);
                v.y = SXY * (acc[mt][nt][h * 2 + 1] + rf + scy[cidx + 1]);
                *(float2*)(orow + nt * 8) = v;
            }
        }
    }
}

// ------------------------------- launch ------------------------------------

extern "C" void kernel_launch(void* const* d_in, const int* in_sizes, int n_in,
                              void* d_out, int out_size) {
    const int* X32 = (const int*)d_in[0];
    const int* Y32 = (const int*)d_in[1];
    float* OUT = (float*)d_out;

    cudaFuncSetAttribute(gemm_bf16_kernel,
                         cudaFuncAttributeMaxDynamicSharedMemorySize, SMEM_TOTAL);

    k_zero_sums<<<16, 256>>>();
    k_pack_xy<<<32768, 256>>>((const int4*)X32, Y32);
    gemm_bf16_kernel<<<dim3(ND / 128, MD / 128), 256, SMEM_TOTAL>>>(OUT);
}

// round 13
// speedup vs baseline: 3.1458x; 1.0057x over previous
#include <cuda_runtime.h>
#include <cstdint>

// ---------------------------------------------------------------------------
// out = sx*sy * ( (X - zpx) @ (Y - zpy) )
// Zero-points folded into the bf16 pack (x+25, y-18 are exact in bf16),
// so the GEMM needs NO corrections at all.
// Inputs are INT32 (harness canonical), values in [-128,127].
// Engine: legacy bf16 HMMA (m16n8k16.f32.bf16.bf16.f32).
// Prepass packs PRE-SWIZZLED bf16 slabs (16KB per 128x64 tile).
// GEMM: 128(M)x64(N) CTA tile, K-stage 64, 3-stage cp.async.bulk pipeline,
// 128 threads (4 warps, warp tile 32x64), 3 CTAs/SM, empty-mbarrier
// stage release (no per-iteration __syncthreads).
// ---------------------------------------------------------------------------

static constexpr int MD = 4096, KD = 4096, ND = 4096;
static constexpr float SXY = 0.0215f * 0.0176f;

__device__ uint16_t g_xa[(size_t)MD * KD];     // 32MB bf16 tiled swizzled (X+25)
__device__ uint16_t g_yb[(size_t)ND * KD];     // 32MB bf16 tiled swizzled (Y-18)^T

// ------------------------------ helpers -----------------------------------

__device__ __forceinline__ uint32_t smem_u32(const void* p) {
    uint32_t a;
    asm("{ .reg .u64 t; cvta.to.shared.u64 t, %1; cvt.u32.u64 %0, t; }"
        : "=r"(a) : "l"(p));
    return a;
}

#define MBARRIER_INIT(addr, cnt) \
    asm volatile("mbarrier.init.shared.b64 [%0], %1;" :: "r"(addr), "r"(cnt) : "memory")

#define MBARRIER_ARRIVE(addr) \
    asm volatile("mbarrier.arrive.shared.b64 _, [%0];" :: "r"(addr) : "memory")

#define MBARRIER_EXPECT_TX(addr, bytes) \
    asm volatile("mbarrier.arrive.expect_tx.shared.b64 _, [%0], %1;" \
                 :: "r"(addr), "r"(bytes) : "memory")

#define MBARRIER_WAIT_PARITY(addr, ph) do {                                         \
    uint32_t _m = (uint32_t)(addr); uint32_t _p = (uint32_t)(ph); uint32_t _d;      \
    asm volatile("{\n\t.reg .pred p;\n\t"                                           \
        "mbarrier.try_wait.parity.acquire.cta.shared::cta.b64 p, [%1], %2;\n\t"     \
        "selp.b32 %0, 1, 0, p;\n\t}"                                                \
        : "=r"(_d) : "r"(_m), "r"(_p) : "memory");                                  \
    if (!_d) {                                                                      \
        asm volatile("{\n\t.reg .pred P1;\n\t"                                      \
            "WL%=:\n\t"                                                             \
            "mbarrier.try_wait.parity.acquire.cta.shared::cta.b64 P1, [%0], %1, 0x989680;\n\t" \
            "@P1 bra.uni WD%=;\n\t"                                                 \
            "bra.uni WL%=;\n\t"                                                     \
            "WD%=:\n\t}"                                                            \
            :: "r"(_m), "r"(_p) : "memory");                                        \
    } } while (0)

__device__ __forceinline__ void bulk_g2s(uint32_t dst, const void* src,
                                         uint32_t bytes, uint32_t mbar) {
    asm volatile(
        "cp.async.bulk.shared::cluster.global.mbarrier::complete_tx::bytes "
        "[%0], [%1], %2, [%3];"
        :: "r"(dst), "l"(src), "r"(bytes), "r"(mbar) : "memory");
}

#define LDSM4(r0, r1, r2, r3, addr) \
    asm volatile("ldmatrix.sync.aligned.m8n8.x4.shared.b16 {%0,%1,%2,%3}, [%4];" \
                 : "=r"(r0), "=r"(r1), "=r"(r2), "=r"(r3) : "r"(addr))

#define MMA_BF16(d, a0, a1, a2, a3, b0, b1) \
    asm volatile("mma.sync.aligned.m16n8k16.row.col.f32.bf16.bf16.f32 " \
                 "{%0,%1,%2,%3},{%4,%5,%6,%7},{%8,%9},{%0,%1,%2,%3};" \
                 : "+f"((d)[0]), "+f"((d)[1]), "+f"((d)[2]), "+f"((d)[3]) \
                 : "r"(a0), "r"(a1), "r"(a2), "r"(a3), "r"(b0), "r"(b1))

// bf16 slab: rows x 128B (64 bf16). SW128 over 16B slots, slot ^= (r&7).
__device__ __forceinline__ uint32_t soff16(int r, int c16) {
    return (uint32_t)(r * 128 + ((c16 ^ (r & 7)) * 16));
}
__device__ __forceinline__ uint32_t slab_elem(int r, int kk) {
    return soff16(r, kk >> 3) + (kk & 7) * 2;
}

// exact int -> bf16 bits (|v| < 512 exact in bf16)
__device__ __forceinline__ uint16_t i2bf(int v) {
    return (uint16_t)(__float_as_uint((float)v) >> 16);
}

// ------------------------------ prepass ------------------------------------
// blocks [0,16384): pack X+25 ; blocks [16384,32768): pack+transpose Y-18

__global__ void k_pack_xy(const int4* __restrict__ qx, const int* __restrict__ Y) {
    if (blockIdx.x < 16384) {
        size_t i = (size_t)blockIdx.x * 256 + threadIdx.x;
        int4 v = qx[i];
        size_t e = i * 4;
        int m = (int)(e >> 12);
        int k = (int)(e & 4095);
        uint32_t lo = (uint32_t)i2bf(v.x + 25) | ((uint32_t)i2bf(v.y + 25) << 16);
        uint32_t hi = (uint32_t)i2bf(v.z + 25) | ((uint32_t)i2bf(v.w + 25) << 16);
        size_t dst = ((size_t)(m >> 7) * 64 + (k >> 6)) * 16384 + slab_elem(m & 127, k & 63);
        uint2 w; w.x = lo; w.y = hi;
        *(uint2*)((char*)g_xa + dst) = w;
    } else {
        __shared__ int8_t tile[32][36];
        int bx = blockIdx.x - 16384;
        int n0 = (bx & 127) * 32, k0 = (bx >> 7) * 32;
        int t = threadIdx.x;
        {
            int k = t >> 3, nq = (t & 7) * 4;
            int4 v = *(const int4*)(Y + (size_t)(k0 + k) * ND + n0 + nq);
            tile[nq + 0][k] = (int8_t)v.x;
            tile[nq + 1][k] = (int8_t)v.y;
            tile[nq + 2][k] = (int8_t)v.z;
            tile[nq + 3][k] = (int8_t)v.w;
        }
        __syncthreads();
        {
            int nl = t >> 3, kq = (t & 7) * 4;
            int e0 = tile[nl][kq + 0] - 18, e1 = tile[nl][kq + 1] - 18;
            int e2 = tile[nl][kq + 2] - 18, e3 = tile[nl][kq + 3] - 18;
            int n = n0 + nl, k = k0 + kq;
            uint32_t lo = (uint32_t)i2bf(e0) | ((uint32_t)i2bf(e1) << 16);
            uint32_t hi = (uint32_t)i2bf(e2) | ((uint32_t)i2bf(e3) << 16);
            size_t dst = ((size_t)(n >> 7) * 64 + (k >> 6)) * 16384 + slab_elem(n & 127, k & 63);
            uint2 w; w.x = lo; w.y = hi;
            *(uint2*)((char*)g_yb + dst) = w;
        }
    }
}

// ------------------------------- GEMM -------------------------------------
// CTA tile 128(M) x 64(N); stage = A(16KB) + B(8KB) = 24KB; 3 stages + 1KB.
// 128 threads = 4 warps stacked in M (warp tile 32x64). 3 CTAs/SM.
// full[s] at +s*8 (tx), empty[s] at +32+s*8 (count 4).

static constexpr int STAGES = 3;
static constexpr int STAGE_BYTES = 24576;
static constexpr int STAGE0_OFF = 1024;
static constexpr int SMEM_TOTAL = STAGE0_OFF + STAGES * STAGE_BYTES;  // 74752
static constexpr int KITERS = KD / 64;                                // 64

__global__ void __launch_bounds__(128, 3)
gemm_bf16_kernel(float* __restrict__ OUT) {
    extern __shared__ char smem[];
    const uint32_t sbase = smem_u32(smem);
    const uint32_t stg = sbase + STAGE0_OFF;
    const int tid = threadIdx.x;
    const int lane = tid & 31;
    const int wm = tid >> 5;                // warp = M quadrant (32 rows)
    const int m0 = blockIdx.y * 128;
    const int n0 = blockIdx.x * 64;

    const int sel = lane >> 3;              // ldmatrix matrix id
    const int l7  = lane & 7;

    const char* aslab = (const char*)g_xa + (size_t)(m0 >> 7) * 64 * 16384;
    const char* bslab = (const char*)g_yb + (size_t)(n0 >> 7) * 64 * 16384
                        + (size_t)(n0 & 64) * 128;   // 64-row half of the slab

    if (tid == 0) {
#pragma unroll
        for (int s = 0; s < STAGES; s++) {
            MBARRIER_INIT(sbase + s * 8, 1);            // full: tx-based
            MBARRIER_INIT(sbase + 32 + s * 8, 4);       // empty: 4 warps
        }
        asm volatile("fence.proxy.async.shared::cta;" ::: "memory");
    }
    __syncthreads();

    if (tid == 0) {
#pragma unroll
        for (int p = 0; p < STAGES; p++) {
            MBARRIER_EXPECT_TX(sbase + p * 8, STAGE_BYTES);
            bulk_g2s(stg + p * STAGE_BYTES,         aslab + (size_t)p * 16384, 16384, sbase + p * 8);
            bulk_g2s(stg + p * STAGE_BYTES + 16384, bslab + (size_t)p * 16384, 8192,  sbase + p * 8);
        }
    }

    float acc[2][8][4];
#pragma unroll
    for (int i = 0; i < 2; i++)
#pragma unroll
        for (int j = 0; j < 8; j++)
#pragma unroll
            for (int q = 0; q < 4; q++) acc[i][j][q] = 0.0f;

    int s = 0, ph = 0;
    for (int it = 0; it < KITERS; it++) {
        MBARRIER_WAIT_PARITY(sbase + s * 8, ph);        // full[s]

        const uint32_t sA = stg + s * STAGE_BYTES;
        const uint32_t sB = sA + 16384;

#pragma unroll
        for (int kq = 0; kq < 4; kq++) {          // 4 x k16 per stage
            uint32_t a[2][4];
#pragma unroll
            for (int mt = 0; mt < 2; mt++) {
                int row = wm * 32 + mt * 16 + l7 + (sel & 1) * 8;
                int c16 = kq * 2 + (sel >> 1);
                LDSM4(a[mt][0], a[mt][1], a[mt][2], a[mt][3], sA + soff16(row, c16));
            }
            uint32_t b[4][4];
#pragma unroll
            for (int np = 0; np < 4; np++) {
                int row = np * 16 + (sel >> 1) * 8 + l7;       // 0..63
                int c16 = kq * 2 + (sel & 1);
                LDSM4(b[np][0], b[np][1], b[np][2], b[np][3], sB + soff16(row, c16));
            }
#pragma unroll
            for (int np = 0; np < 4; np++) {
                MMA_BF16(acc[0][np * 2 + 0], a[0][0], a[0][1], a[0][2], a[0][3],
                         b[np][0], b[np][1]);
                MMA_BF16(acc[0][np * 2 + 1], a[0][0], a[0][1], a[0][2], a[0][3],
                         b[np][2], b[np][3]);
                MMA_BF16(acc[1][np * 2 + 0], a[1][0], a[1][1], a[1][2], a[1][3],
                         b[np][0], b[np][1]);
                MMA_BF16(acc[1][np * 2 + 1], a[1][0], a[1][1], a[1][2], a[1][3],
                         b[np][2], b[np][3]);
            }
        }

        // warp done reading stage s -> release it
        if (lane == 0) MBARRIER_ARRIVE(sbase + 32 + s * 8);

        // producer refill
        if (tid == 0 && it + STAGES < KITERS) {
            MBARRIER_WAIT_PARITY(sbase + 32 + s * 8, ph);   // empty[s]
            MBARRIER_EXPECT_TX(sbase + s * 8, STAGE_BYTES);
            bulk_g2s(stg + s * STAGE_BYTES,         aslab + (size_t)(it + STAGES) * 16384, 16384, sbase + s * 8);
            bulk_g2s(stg + s * STAGE_BYTES + 16384, bslab + (size_t)(it + STAGES) * 16384, 8192,  sbase + s * 8);
        }
        if (++s == STAGES) { s = 0; ph ^= 1; }
    }

    // epilogue: pure scale, no corrections
    const int gid = lane >> 2, tig = lane & 3;
#pragma unroll
    for (int mt = 0; mt < 2; mt++) {
#pragma unroll
        for (int h = 0; h < 2; h++) {
            const int rloc = wm * 32 + mt * 16 + h * 8 + gid;
            float* orow = OUT + (size_t)(m0 + rloc) * ND + n0 + tig * 2;
#pragma unroll
            for (int nt = 0; nt < 8; nt++) {
                float2 v;
                v.x = SXY * acc[mt][nt][h * 2 + 0];
                v.y = SXY * acc[mt][nt][h * 2 + 1];
                *(float2*)(orow + nt * 8) = v;
            }
        }
    }
}

// ------------------------------- launch ------------------------------------

extern "C" void kernel_launch(void* const* d_in, const int* in_sizes, int n_in,
                              void* d_out, int out_size) {
    const int* X32 = (const int*)d_in[0];
    const int* Y32 = (const int*)d_in[1];
    float* OUT = (float*)d_out;

    cudaFuncSetAttribute(gemm_bf16_kernel,
                         cudaFuncAttributeMaxDynamicSharedMemorySize, SMEM_TOTAL);

    k_pack_xy<<<32768, 256>>>((const int4*)X32, Y32);
    gemm_bf16_kernel<<<dim3(ND / 64, MD / 128), 128, SMEM_TOTAL>>>(OUT);
}

// round 14
// speedup vs baseline: 3.1846x; 1.0123x over previous
#include <cuda_runtime.h>
#include <cstdint>

// ---------------------------------------------------------------------------
// out = sx*sy * ( (X+25) @ (Y-18) )   [zero-points folded into bf16 pack]
// Inputs are INT32 (harness canonical), values in [-128,127].
// Engine: legacy bf16 HMMA (m16n8k16.f32.bf16.bf16.f32); ints exact in bf16.
// Prepass packs PRE-SWIZZLED bf16 slabs (16KB per 128x64 tile), 16B stores.
// GEMM: 128(M)x64(N) CTA tile, K-stage 64, 3-stage cp.async.bulk pipeline,
// 128 threads (4 warps), 3 CTAs/SM, empty-mbarrier stage release with
// ROTATING producer warp (it&3) and relaxed empty-wait.
// ---------------------------------------------------------------------------

static constexpr int MD = 4096, KD = 4096, ND = 4096;
static constexpr float SXY = 0.0215f * 0.0176f;

__device__ uint16_t g_xa[(size_t)MD * KD];     // 32MB bf16 tiled swizzled (X+25)
__device__ uint16_t g_yb[(size_t)ND * KD];     // 32MB bf16 tiled swizzled (Y-18)^T

// ------------------------------ helpers -----------------------------------

__device__ __forceinline__ uint32_t smem_u32(const void* p) {
    uint32_t a;
    asm("{ .reg .u64 t; cvta.to.shared.u64 t, %1; cvt.u32.u64 %0, t; }"
        : "=r"(a) : "l"(p));
    return a;
}

#define MBARRIER_INIT(addr, cnt) \
    asm volatile("mbarrier.init.shared.b64 [%0], %1;" :: "r"(addr), "r"(cnt) : "memory")

#define MBARRIER_ARRIVE(addr) \
    asm volatile("mbarrier.arrive.shared.b64 _, [%0];" :: "r"(addr) : "memory")

#define MBARRIER_EXPECT_TX(addr, bytes) \
    asm volatile("mbarrier.arrive.expect_tx.shared.b64 _, [%0], %1;" \
                 :: "r"(addr), "r"(bytes) : "memory")

#define MBARRIER_WAIT_PARITY(addr, ph) do {                                         \
    uint32_t _m = (uint32_t)(addr); uint32_t _p = (uint32_t)(ph); uint32_t _d;      \
    asm volatile("{\n\t.reg .pred p;\n\t"                                           \
        "mbarrier.try_wait.parity.acquire.cta.shared::cta.b64 p, [%1], %2;\n\t"     \
        "selp.b32 %0, 1, 0, p;\n\t}"                                                \
        : "=r"(_d) : "r"(_m), "r"(_p) : "memory");                                  \
    if (!_d) {                                                                      \
        asm volatile("{\n\t.reg .pred P1;\n\t"                                      \
            "WL%=:\n\t"                                                             \
            "mbarrier.try_wait.parity.acquire.cta.shared::cta.b64 P1, [%0], %1, 0x989680;\n\t" \
            "@P1 bra.uni WD%=;\n\t"                                                 \
            "bra.uni WL%=;\n\t"                                                     \
            "WD%=:\n\t}"                                                            \
            :: "r"(_m), "r"(_p) : "memory");                                        \
    } } while (0)

// relaxed: post-wait accesses are async-proxy (cp.async.bulk) only
#define MBARRIER_WAIT_PARITY_RELAXED(addr, ph) do {                                 \
    uint32_t _m = (uint32_t)(addr); uint32_t _p = (uint32_t)(ph); uint32_t _d;      \
    asm volatile("{\n\t.reg .pred p;\n\t"                                           \
        "mbarrier.try_wait.parity.relaxed.cta.shared::cta.b64 p, [%1], %2;\n\t"     \
        "selp.b32 %0, 1, 0, p;\n\t}"                                                \
        : "=r"(_d) : "r"(_m), "r"(_p) : "memory");                                  \
    if (!_d) {                                                                      \
        asm volatile("{\n\t.reg .pred P1;\n\t"                                      \
            "WL%=:\n\t"                                                             \
            "mbarrier.try_wait.parity.relaxed.cta.shared::cta.b64 P1, [%0], %1, 0x989680;\n\t" \
            "@P1 bra.uni WD%=;\n\t"                                                 \
            "bra.uni WL%=;\n\t"                                                     \
            "WD%=:\n\t}"                                                            \
            :: "r"(_m), "r"(_p) : "memory");                                        \
    } } while (0)

__device__ __forceinline__ void bulk_g2s(uint32_t dst, const void* src,
                                         uint32_t bytes, uint32_t mbar) {
    asm volatile(
        "cp.async.bulk.shared::cluster.global.mbarrier::complete_tx::bytes "
        "[%0], [%1], %2, [%3];"
        :: "r"(dst), "l"(src), "r"(bytes), "r"(mbar) : "memory");
}

#define LDSM4(r0, r1, r2, r3, addr) \
    asm volatile("ldmatrix.sync.aligned.m8n8.x4.shared.b16 {%0,%1,%2,%3}, [%4];" \
                 : "=r"(r0), "=r"(r1), "=r"(r2), "=r"(r3) : "r"(addr))

#define MMA_BF16(d, a0, a1, a2, a3, b0, b1) \
    asm volatile("mma.sync.aligned.m16n8k16.row.col.f32.bf16.bf16.f32 " \
                 "{%0,%1,%2,%3},{%4,%5,%6,%7},{%8,%9},{%0,%1,%2,%3};" \
                 : "+f"((d)[0]), "+f"((d)[1]), "+f"((d)[2]), "+f"((d)[3]) \
                 : "r"(a0), "r"(a1), "r"(a2), "r"(a3), "r"(b0), "r"(b1))

// bf16 slab: rows x 128B (64 bf16). SW128 over 16B slots, slot ^= (r&7).
__device__ __forceinline__ uint32_t soff16(int r, int c16) {
    return (uint32_t)(r * 128 + ((c16 ^ (r & 7)) * 16));
}

// exact int -> bf16 bits (|v| < 512 exact in bf16)
__device__ __forceinline__ uint16_t i2bf(int v) {
    return (uint16_t)(__float_as_uint((float)v) >> 16);
}

__device__ __forceinline__ uint32_t bfpair(int lo, int hi) {
    return (uint32_t)i2bf(lo) | ((uint32_t)i2bf(hi) << 16);
}

// ------------------------------ prepass ------------------------------------
// blocks [0,8192): pack X+25 (16B stores)
// blocks [8192,16384): pack+transpose Y-18 via 64k x 32n smem tiles (16B stores)

__global__ void k_pack_xy(const int4* __restrict__ qx, const int* __restrict__ Y) {
    __shared__ int8_t tile[64][36];
    if (blockIdx.x < 8192) {
        size_t i = (size_t)blockIdx.x * 256 + threadIdx.x;   // 8-elem group
        size_t e = i * 8;
        int m = (int)(e >> 12);
        int k = (int)(e & 4095);                             // multiple of 8
        int4 v0 = qx[i * 2];
        int4 v1 = qx[i * 2 + 1];
        uint4 w;
        w.x = bfpair(v0.x + 25, v0.y + 25);
        w.y = bfpair(v0.z + 25, v0.w + 25);
        w.z = bfpair(v1.x + 25, v1.y + 25);
        w.w = bfpair(v1.z + 25, v1.w + 25);
        size_t dst = ((size_t)(m >> 7) * 64 + (k >> 6)) * 16384
                   + soff16(m & 127, (k & 63) >> 3);
        *(uint4*)((char*)g_xa + dst) = w;
    } else {
        int bx = blockIdx.x - 8192;
        int n0 = (bx & 127) * 32;         // 128 n-blocks of 32
        int k0 = (bx >> 7) * 64;          // 64 k-blocks of 64
        int t = threadIdx.x;
        // load 64 k-rows x 32 n ints: 512 int4, 2 per thread
        {
            int j0 = t * 2;
#pragma unroll
            for (int u = 0; u < 2; u++) {
                int j = j0 + u;                 // 0..511
                int kr = j >> 3;                // 8 int4 per k-row
                int nc = (j & 7) * 4;
                int4 v = *(const int4*)(Y + (size_t)(k0 + kr) * ND + n0 + nc);
                tile[kr][nc + 0] = (int8_t)v.x;
                tile[kr][nc + 1] = (int8_t)v.y;
                tile[kr][nc + 2] = (int8_t)v.z;
                tile[kr][nc + 3] = (int8_t)v.w;
            }
        }
        __syncthreads();
        // write: 32 n-rows x 64 kk; thread -> (nr = t>>3, kq = (t&7)*8), 16B
        {
            int nr = t >> 3;
            int kq = (t & 7) * 8;
            int n = n0 + nr;
            uint4 w;
            w.x = bfpair(tile[kq + 0][nr] - 18, tile[kq + 1][nr] - 18);
            w.y = bfpair(tile[kq + 2][nr] - 18, tile[kq + 3][nr] - 18);
            w.z = bfpair(tile[kq + 4][nr] - 18, tile[kq + 5][nr] - 18);
            w.w = bfpair(tile[kq + 6][nr] - 18, tile[kq + 7][nr] - 18);
            size_t dst = ((size_t)(n >> 7) * 64 + (k0 >> 6)) * 16384
                       + soff16(n & 127, kq >> 3);
            *(uint4*)((char*)g_yb + dst) = w;
        }
    }
}

// ------------------------------- GEMM -------------------------------------
// CTA tile 128(M) x 64(N); stage = A(16KB) + B(8KB) = 24KB; 3 stages + 1KB.
// 128 threads = 4 warps stacked in M (warp tile 32x64). 3 CTAs/SM.
// full[s] at +s*8 (tx), empty[s] at +32+s*8 (count 4). Producer = warp (it&3).

static constexpr int STAGES = 3;
static constexpr int STAGE_BYTES = 24576;
static constexpr int STAGE0_OFF = 1024;
static constexpr int SMEM_TOTAL = STAGE0_OFF + STAGES * STAGE_BYTES;  // 74752
static constexpr int KITERS = KD / 64;                                // 64

__global__ void __launch_bounds__(128, 3)
gemm_bf16_kernel(float* __restrict__ OUT) {
    extern __shared__ char smem[];
    const uint32_t sbase = smem_u32(smem);
    const uint32_t stg = sbase + STAGE0_OFF;
    const int tid = threadIdx.x;
    const int lane = tid & 31;
    const int wm = tid >> 5;                // warp = M quadrant (32 rows)
    const int m0 = blockIdx.y * 128;
    const int n0 = blockIdx.x * 64;

    const int sel = lane >> 3;              // ldmatrix matrix id
    const int l7  = lane & 7;

    const char* aslab = (const char*)g_xa + (size_t)(m0 >> 7) * 64 * 16384;
    const char* bslab = (const char*)g_yb + (size_t)(n0 >> 7) * 64 * 16384
                        + (size_t)(n0 & 64) * 128;   // 64-row half of the slab

    if (tid == 0) {
#pragma unroll
        for (int s = 0; s < STAGES; s++) {
            MBARRIER_INIT(sbase + s * 8, 1);            // full: tx-based
            MBARRIER_INIT(sbase + 32 + s * 8, 4);       // empty: 4 warps
        }
        asm volatile("fence.proxy.async.shared::cta;" ::: "memory");
    }
    __syncthreads();

    if (tid == 0) {
#pragma unroll
        for (int p = 0; p < STAGES; p++) {
            MBARRIER_EXPECT_TX(sbase + p * 8, STAGE_BYTES);
            bulk_g2s(stg + p * STAGE_BYTES,         aslab + (size_t)p * 16384, 16384, sbase + p * 8);
            bulk_g2s(stg + p * STAGE_BYTES + 16384, bslab + (size_t)p * 16384, 8192,  sbase + p * 8);
        }
    }

    float acc[2][8][4];
#pragma unroll
    for (int i = 0; i < 2; i++)
#pragma unroll
        for (int j = 0; j < 8; j++)
#pragma unroll
            for (int q = 0; q < 4; q++) acc[i][j][q] = 0.0f;

    int s = 0, ph = 0;
    for (int it = 0; it < KITERS; it++) {
        MBARRIER_WAIT_PARITY(sbase + s * 8, ph);        // full[s]

        const uint32_t sA = stg + s * STAGE_BYTES;
        const uint32_t sB = sA + 16384;

#pragma unroll
        for (int kq = 0; kq < 4; kq++) {          // 4 x k16 per stage
            uint32_t a[2][4];
#pragma unroll
            for (int mt = 0; mt < 2; mt++) {
                int row = wm * 32 + mt * 16 + l7 + (sel & 1) * 8;
                int c16 = kq * 2 + (sel >> 1);
                LDSM4(a[mt][0], a[mt][1], a[mt][2], a[mt][3], sA + soff16(row, c16));
            }
            uint32_t b[4][4];
#pragma unroll
            for (int np = 0; np < 4; np++) {
                int row = np * 16 + (sel >> 1) * 8 + l7;       // 0..63
                int c16 = kq * 2 + (sel & 1);
                LDSM4(b[np][0], b[np][1], b[np][2], b[np][3], sB + soff16(row, c16));
            }
#pragma unroll
            for (int np = 0; np < 4; np++) {
                MMA_BF16(acc[0][np * 2 + 0], a[0][0], a[0][1], a[0][2], a[0][3],
                         b[np][0], b[np][1]);
                MMA_BF16(acc[0][np * 2 + 1], a[0][0], a[0][1], a[0][2], a[0][3],
                         b[np][2], b[np][3]);
                MMA_BF16(acc[1][np * 2 + 0], a[1][0], a[1][1], a[1][2], a[1][3],
                         b[np][0], b[np][1]);
                MMA_BF16(acc[1][np * 2 + 1], a[1][0], a[1][1], a[1][2], a[1][3],
                         b[np][2], b[np][3]);
            }
        }

        // warp done reading stage s -> release it
        if (lane == 0) MBARRIER_ARRIVE(sbase + 32 + s * 8);

        // rotating producer: warp (it&3) refills stage s with tile it+3
        if (wm == (it & 3) && lane == 0 && it + STAGES < KITERS) {
            MBARRIER_WAIT_PARITY_RELAXED(sbase + 32 + s * 8, ph);   // empty[s]
            MBARRIER_EXPECT_TX(sbase + s * 8, STAGE_BYTES);
            bulk_g2s(stg + s * STAGE_BYTES,         aslab + (size_t)(it + STAGES) * 16384, 16384, sbase + s * 8);
            bulk_g2s(stg + s * STAGE_BYTES + 16384, bslab + (size_t)(it + STAGES) * 16384, 8192,  sbase + s * 8);
        }
        if (++s == STAGES) { s = 0; ph ^= 1; }
    }

    // epilogue: pure scale, no corrections
    const int gid = lane >> 2, tig = lane & 3;
#pragma unroll
    for (int mt = 0; mt < 2; mt++) {
#pragma unroll
        for (int h = 0; h < 2; h++) {
            const int rloc = wm * 32 + mt * 16 + h * 8 + gid;
            float* orow = OUT + (size_t)(m0 + rloc) * ND + n0 + tig * 2;
#pragma unroll
            for (int nt = 0; nt < 8; nt++) {
                float2 v;
                v.x = SXY * acc[mt][nt][h * 2 + 0];
                v.y = SXY * acc[mt][nt][h * 2 + 1];
                *(float2*)(orow + nt * 8) = v;
            }
        }
    }
}

// ------------------------------- launch ------------------------------------

extern "C" void kernel_launch(void* const* d_in, const int* in_sizes, int n_in,
                              void* d_out, int out_size) {
    const int* X32 = (const int*)d_in[0];
    const int* Y32 = (const int*)d_in[1];
    float* OUT = (float*)d_out;

    cudaFuncSetAttribute(gemm_bf16_kernel,
                         cudaFuncAttributeMaxDynamicSharedMemorySize, SMEM_TOTAL);

    k_pack_xy<<<16384, 256>>>((const int4*)X32, Y32);
    gemm_bf16_kernel<<<dim3(ND / 64, MD / 128), 128, SMEM_TOTAL>>>(OUT);
}

// round 15
// speedup vs baseline: 3.1950x; 1.0032x over previous
#include <cuda_runtime.h>
#include <cstdint>

// ---------------------------------------------------------------------------
// out = sx*sy * ( (X+25) @ (Y-18) )   [zero-points folded into bf16 pack]
// Inputs are INT32 (harness canonical), values in [-128,127].
// Engine: legacy bf16 HMMA (m16n8k16.f32.bf16.bf16.f32); ints exact in bf16.
// Prepass packs PRE-SWIZZLED bf16 slabs (16KB per 128x64 tile), 16B stores.
// GEMM: 128(M)x64(N) CTA tile, K-stage 64, 3-stage cp.async.bulk pipeline,
// 128 threads (4 warps), 3 CTAs/SM. Single tid-0 producer with ACQUIRE
// empty-wait (known-good R13 ordering; R14's rotating/relaxed producer
// introduced a one-slot race -> reverted).
// ---------------------------------------------------------------------------

static constexpr int MD = 4096, KD = 4096, ND = 4096;
static constexpr float SXY = 0.0215f * 0.0176f;

__device__ uint16_t g_xa[(size_t)MD * KD];     // 32MB bf16 tiled swizzled (X+25)
__device__ uint16_t g_yb[(size_t)ND * KD];     // 32MB bf16 tiled swizzled (Y-18)^T

// ------------------------------ helpers -----------------------------------

__device__ __forceinline__ uint32_t smem_u32(const void* p) {
    uint32_t a;
    asm("{ .reg .u64 t; cvta.to.shared.u64 t, %1; cvt.u32.u64 %0, t; }"
        : "=r"(a) : "l"(p));
    return a;
}

#define MBARRIER_INIT(addr, cnt) \
    asm volatile("mbarrier.init.shared.b64 [%0], %1;" :: "r"(addr), "r"(cnt) : "memory")

#define MBARRIER_ARRIVE(addr) \
    asm volatile("mbarrier.arrive.shared.b64 _, [%0];" :: "r"(addr) : "memory")

#define MBARRIER_EXPECT_TX(addr, bytes) \
    asm volatile("mbarrier.arrive.expect_tx.shared.b64 _, [%0], %1;" \
                 :: "r"(addr), "r"(bytes) : "memory")

#define MBARRIER_WAIT_PARITY(addr, ph) do {                                         \
    uint32_t _m = (uint32_t)(addr); uint32_t _p = (uint32_t)(ph); uint32_t _d;      \
    asm volatile("{\n\t.reg .pred p;\n\t"                                           \
        "mbarrier.try_wait.parity.acquire.cta.shared::cta.b64 p, [%1], %2;\n\t"     \
        "selp.b32 %0, 1, 0, p;\n\t}"                                                \
        : "=r"(_d) : "r"(_m), "r"(_p) : "memory");                                  \
    if (!_d) {                                                                      \
        asm volatile("{\n\t.reg .pred P1;\n\t"                                      \
            "WL%=:\n\t"                                                             \
            "mbarrier.try_wait.parity.acquire.cta.shared::cta.b64 P1, [%0], %1, 0x989680;\n\t" \
            "@P1 bra.uni WD%=;\n\t"                                                 \
            "bra.uni WL%=;\n\t"                                                     \
            "WD%=:\n\t}"                                                            \
            :: "r"(_m), "r"(_p) : "memory");                                        \
    } } while (0)

__device__ __forceinline__ void bulk_g2s(uint32_t dst, const void* src,
                                         uint32_t bytes, uint32_t mbar) {
    asm volatile(
        "cp.async.bulk.shared::cluster.global.mbarrier::complete_tx::bytes "
        "[%0], [%1], %2, [%3];"
        :: "r"(dst), "l"(src), "r"(bytes), "r"(mbar) : "memory");
}

#define LDSM4(r0, r1, r2, r3, addr) \
    asm volatile("ldmatrix.sync.aligned.m8n8.x4.shared.b16 {%0,%1,%2,%3}, [%4];" \
                 : "=r"(r0), "=r"(r1), "=r"(r2), "=r"(r3) : "r"(addr))

#define MMA_BF16(d, a0, a1, a2, a3, b0, b1) \
    asm volatile("mma.sync.aligned.m16n8k16.row.col.f32.bf16.bf16.f32 " \
                 "{%0,%1,%2,%3},{%4,%5,%6,%7},{%8,%9},{%0,%1,%2,%3};" \
                 : "+f"((d)[0]), "+f"((d)[1]), "+f"((d)[2]), "+f"((d)[3]) \
                 : "r"(a0), "r"(a1), "r"(a2), "r"(a3), "r"(b0), "r"(b1))

// bf16 slab: rows x 128B (64 bf16). SW128 over 16B slots, slot ^= (r&7).
__device__ __forceinline__ uint32_t soff16(int r, int c16) {
    return (uint32_t)(r * 128 + ((c16 ^ (r & 7)) * 16));
}

// exact int -> bf16 bits (|v| < 512 exact in bf16)
__device__ __forceinline__ uint16_t i2bf(int v) {
    return (uint16_t)(__float_as_uint((float)v) >> 16);
}

__device__ __forceinline__ uint32_t bfpair(int lo, int hi) {
    return (uint32_t)i2bf(lo) | ((uint32_t)i2bf(hi) << 16);
}

// ------------------------------ prepass ------------------------------------
// blocks [0,8192): pack X+25 (16B stores)
// blocks [8192,16384): pack+transpose Y-18 via 64k x 32n smem tiles (16B stores)

__global__ void k_pack_xy(const int4* __restrict__ qx, const int* __restrict__ Y) {
    __shared__ int8_t tile[64][36];
    if (blockIdx.x < 8192) {
        size_t i = (size_t)blockIdx.x * 256 + threadIdx.x;   // 8-elem group
        size_t e = i * 8;
        int m = (int)(e >> 12);
        int k = (int)(e & 4095);                             // multiple of 8
        int4 v0 = qx[i * 2];
        int4 v1 = qx[i * 2 + 1];
        uint4 w;
        w.x = bfpair(v0.x + 25, v0.y + 25);
        w.y = bfpair(v0.z + 25, v0.w + 25);
        w.z = bfpair(v1.x + 25, v1.y + 25);
        w.w = bfpair(v1.z + 25, v1.w + 25);
        size_t dst = ((size_t)(m >> 7) * 64 + (k >> 6)) * 16384
                   + soff16(m & 127, (k & 63) >> 3);
        *(uint4*)((char*)g_xa + dst) = w;
    } else {
        int bx = blockIdx.x - 8192;
        int n0 = (bx & 127) * 32;         // 128 n-blocks of 32
        int k0 = (bx >> 7) * 64;          // 64 k-blocks of 64
        int t = threadIdx.x;
        {
            int j0 = t * 2;
#pragma unroll
            for (int u = 0; u < 2; u++) {
                int j = j0 + u;                 // 0..511
                int kr = j >> 3;                // 8 int4 per k-row
                int nc = (j & 7) * 4;
                int4 v = *(const int4*)(Y + (size_t)(k0 + kr) * ND + n0 + nc);
                tile[kr][nc + 0] = (int8_t)v.x;
                tile[kr][nc + 1] = (int8_t)v.y;
                tile[kr][nc + 2] = (int8_t)v.z;
                tile[kr][nc + 3] = (int8_t)v.w;
            }
        }
        __syncthreads();
        {
            int nr = t >> 3;
            int kq = (t & 7) * 8;
            int n = n0 + nr;
            uint4 w;
            w.x = bfpair(tile[kq + 0][nr] - 18, tile[kq + 1][nr] - 18);
            w.y = bfpair(tile[kq + 2][nr] - 18, tile[kq + 3][nr] - 18);
            w.z = bfpair(tile[kq + 4][nr] - 18, tile[kq + 5][nr] - 18);
            w.w = bfpair(tile[kq + 6][nr] - 18, tile[kq + 7][nr] - 18);
            size_t dst = ((size_t)(n >> 7) * 64 + (k0 >> 6)) * 16384
                       + soff16(n & 127, kq >> 3);
            *(uint4*)((char*)g_yb + dst) = w;
        }
    }
}

// ------------------------------- GEMM -------------------------------------
// CTA tile 128(M) x 64(N); stage = A(16KB) + B(8KB) = 24KB; 3 stages + 1KB.
// 128 threads = 4 warps stacked in M (warp tile 32x64). 3 CTAs/SM.
// full[s] at +s*8 (tx), empty[s] at +32+s*8 (count 4). Producer = tid 0.

static constexpr int STAGES = 3;
static constexpr int STAGE_BYTES = 24576;
static constexpr int STAGE0_OFF = 1024;
static constexpr int SMEM_TOTAL = STAGE0_OFF + STAGES * STAGE_BYTES;  // 74752
static constexpr int KITERS = KD / 64;                                // 64

__global__ void __launch_bounds__(128, 3)
gemm_bf16_kernel(float* __restrict__ OUT) {
    extern __shared__ char smem[];
    const uint32_t sbase = smem_u32(smem);
    const uint32_t stg = sbase + STAGE0_OFF;
    const int tid = threadIdx.x;
    const int lane = tid & 31;
    const int wm = tid >> 5;                // warp = M quadrant (32 rows)
    const int m0 = blockIdx.y * 128;
    const int n0 = blockIdx.x * 64;

    const int sel = lane >> 3;              // ldmatrix matrix id
    const int l7  = lane & 7;

    const char* aslab = (const char*)g_xa + (size_t)(m0 >> 7) * 64 * 16384;
    const char* bslab = (const char*)g_yb + (size_t)(n0 >> 7) * 64 * 16384
                        + (size_t)(n0 & 64) * 128;   // 64-row half of the slab

    if (tid == 0) {
#pragma unroll
        for (int s = 0; s < STAGES; s++) {
            MBARRIER_INIT(sbase + s * 8, 1);            // full: tx-based
            MBARRIER_INIT(sbase + 32 + s * 8, 4);       // empty: 4 warps
        }
        asm volatile("fence.proxy.async.shared::cta;" ::: "memory");
    }
    __syncthreads();

    if (tid == 0) {
#pragma unroll
        for (int p = 0; p < STAGES; p++) {
            MBARRIER_EXPECT_TX(sbase + p * 8, STAGE_BYTES);
            bulk_g2s(stg + p * STAGE_BYTES,         aslab + (size_t)p * 16384, 16384, sbase + p * 8);
            bulk_g2s(stg + p * STAGE_BYTES + 16384, bslab + (size_t)p * 16384, 8192,  sbase + p * 8);
        }
    }

    float acc[2][8][4];
#pragma unroll
    for (int i = 0; i < 2; i++)
#pragma unroll
        for (int j = 0; j < 8; j++)
#pragma unroll
            for (int q = 0; q < 4; q++) acc[i][j][q] = 0.0f;

    int s = 0, ph = 0;
    for (int it = 0; it < KITERS; it++) {
        MBARRIER_WAIT_PARITY(sbase + s * 8, ph);        // full[s]

        const uint32_t sA = stg + s * STAGE_BYTES;
        const uint32_t sB = sA + 16384;

#pragma unroll
        for (int kq = 0; kq < 4; kq++) {          // 4 x k16 per stage
            uint32_t a[2][4];
#pragma unroll
            for (int mt = 0; mt < 2; mt++) {
                int row = wm * 32 + mt * 16 + l7 + (sel & 1) * 8;
                int c16 = kq * 2 + (sel >> 1);
                LDSM4(a[mt][0], a[mt][1], a[mt][2], a[mt][3], sA + soff16(row, c16));
            }
            uint32_t b[4][4];
#pragma unroll
            for (int np = 0; np < 4; np++) {
                int row = np * 16 + (sel >> 1) * 8 + l7;       // 0..63
                int c16 = kq * 2 + (sel & 1);
                LDSM4(b[np][0], b[np][1], b[np][2], b[np][3], sB + soff16(row, c16));
            }
#pragma unroll
            for (int np = 0; np < 4; np++) {
                MMA_BF16(acc[0][np * 2 + 0], a[0][0], a[0][1], a[0][2], a[0][3],
                         b[np][0], b[np][1]);
                MMA_BF16(acc[0][np * 2 + 1], a[0][0], a[0][1], a[0][2], a[0][3],
                         b[np][2], b[np][3]);
                MMA_BF16(acc[1][np * 2 + 0], a[1][0], a[1][1], a[1][2], a[1][3],
                         b[np][0], b[np][1]);
                MMA_BF16(acc[1][np * 2 + 1], a[1][0], a[1][1], a[1][2], a[1][3],
                         b[np][2], b[np][3]);
            }
        }

        // warp done reading stage s -> release it
        if (lane == 0) MBARRIER_ARRIVE(sbase + 32 + s * 8);

        // single producer (tid 0), ACQUIRE empty-wait, then refill
        if (tid == 0 && it + STAGES < KITERS) {
            MBARRIER_WAIT_PARITY(sbase + 32 + s * 8, ph);   // empty[s]
            MBARRIER_EXPECT_TX(sbase + s * 8, STAGE_BYTES);
            bulk_g2s(stg + s * STAGE_BYTES,         aslab + (size_t)(it + STAGES) * 16384, 16384, sbase + s * 8);
            bulk_g2s(stg + s * STAGE_BYTES + 16384, bslab + (size_t)(it + STAGES) * 16384, 8192,  sbase + s * 8);
        }
        if (++s == STAGES) { s = 0; ph ^= 1; }
    }

    // epilogue: pure scale, no corrections
    const int gid = lane >> 2, tig = lane & 3;
#pragma unroll
    for (int mt = 0; mt < 2; mt++) {
#pragma unroll
        for (int h = 0; h < 2; h++) {
            const int rloc = wm * 32 + mt * 16 + h * 8 + gid;
            float* orow = OUT + (size_t)(m0 + rloc) * ND + n0 + tig * 2;
#pragma unroll
            for (int nt = 0; nt < 8; nt++) {
                float2 v;
                v.x = SXY * acc[mt][nt][h * 2 + 0];
                v.y = SXY * acc[mt][nt][h * 2 + 1];
                *(float2*)(orow + nt * 8) = v;
            }
        }
    }
}

// ------------------------------- launch ------------------------------------

extern "C" void kernel_launch(void* const* d_in, const int* in_sizes, int n_in,
                              void* d_out, int out_size) {
    const int* X32 = (const int*)d_in[0];
    const int* Y32 = (const int*)d_in[1];
    float* OUT = (float*)d_out;

    cudaFuncSetAttribute(gemm_bf16_kernel,
                         cudaFuncAttributeMaxDynamicSharedMemorySize, SMEM_TOTAL);

    k_pack_xy<<<16384, 256>>>((const int4*)X32, Y32);
    gemm_bf16_kernel<<<dim3(ND / 64, MD / 128), 128, SMEM_TOTAL>>>(OUT);
}

// round 16
// speedup vs baseline: 3.2149x; 1.0062x over previous
#include <cuda_runtime.h>
#include <cstdint>

// ---------------------------------------------------------------------------
// out = sx*sy * ( (X+25) @ (Y-18) )   [zero-points folded into bf16 pack]
// Inputs are INT32 (harness canonical), values in [-128,127].
// Engine: legacy bf16 HMMA (m16n8k16.f32.bf16.bf16.f32); ints exact in bf16.
// Prepass packs PRE-SWIZZLED bf16 slabs (16KB per 128x64 tile), 16B stores.
// GEMM: 128(M)x64(N) CTA tile, K-stage 64, 3-stage cp.async.bulk pipeline.
// Block = 160 threads: 4 MMA warps (warp tile 32x64) + 1 DEDICATED PRODUCER
// warp (bulk-copy refills, acquire empty-wait). 2 CTAs/SM -> 2048 tiles over
// 296 slots = 6.92 waves (wave-quantization loss 1.2% vs 7.8% at 3/SM).
// ---------------------------------------------------------------------------

static constexpr int MD = 4096, KD = 4096, ND = 4096;
static constexpr float SXY = 0.0215f * 0.0176f;

__device__ uint16_t g_xa[(size_t)MD * KD];     // 32MB bf16 tiled swizzled (X+25)
__device__ uint16_t g_yb[(size_t)ND * KD];     // 32MB bf16 tiled swizzled (Y-18)^T

// ------------------------------ helpers -----------------------------------

__device__ __forceinline__ uint32_t smem_u32(const void* p) {
    uint32_t a;
    asm("{ .reg .u64 t; cvta.to.shared.u64 t, %1; cvt.u32.u64 %0, t; }"
        : "=r"(a) : "l"(p));
    return a;
}

#define MBARRIER_INIT(addr, cnt) \
    asm volatile("mbarrier.init.shared.b64 [%0], %1;" :: "r"(addr), "r"(cnt) : "memory")

#define MBARRIER_ARRIVE(addr) \
    asm volatile("mbarrier.arrive.shared.b64 _, [%0];" :: "r"(addr) : "memory")

#define MBARRIER_EXPECT_TX(addr, bytes) \
    asm volatile("mbarrier.arrive.expect_tx.shared.b64 _, [%0], %1;" \
                 :: "r"(addr), "r"(bytes) : "memory")

#define MBARRIER_WAIT_PARITY(addr, ph) do {                                         \
    uint32_t _m = (uint32_t)(addr); uint32_t _p = (uint32_t)(ph); uint32_t _d;      \
    asm volatile("{\n\t.reg .pred p;\n\t"                                           \
        "mbarrier.try_wait.parity.acquire.cta.shared::cta.b64 p, [%1], %2;\n\t"     \
        "selp.b32 %0, 1, 0, p;\n\t}"                                                \
        : "=r"(_d) : "r"(_m), "r"(_p) : "memory");                                  \
    if (!_d) {                                                                      \
        asm volatile("{\n\t.reg .pred P1;\n\t"                                      \
            "WL%=:\n\t"                                                             \
            "mbarrier.try_wait.parity.acquire.cta.shared::cta.b64 P1, [%0], %1, 0x989680;\n\t" \
            "@P1 bra.uni WD%=;\n\t"                                                 \
            "bra.uni WL%=;\n\t"                                                     \
            "WD%=:\n\t}"                                                            \
            :: "r"(_m), "r"(_p) : "memory");                                        \
    } } while (0)

__device__ __forceinline__ void bulk_g2s(uint32_t dst, const void* src,
                                         uint32_t bytes, uint32_t mbar) {
    asm volatile(
        "cp.async.bulk.shared::cluster.global.mbarrier::complete_tx::bytes "
        "[%0], [%1], %2, [%3];"
        :: "r"(dst), "l"(src), "r"(bytes), "r"(mbar) : "memory");
}

#define LDSM4(r0, r1, r2, r3, addr) \
    asm volatile("ldmatrix.sync.aligned.m8n8.x4.shared.b16 {%0,%1,%2,%3}, [%4];" \
                 : "=r"(r0), "=r"(r1), "=r"(r2), "=r"(r3) : "r"(addr))

#define MMA_BF16(d, a0, a1, a2, a3, b0, b1) \
    asm volatile("mma.sync.aligned.m16n8k16.row.col.f32.bf16.bf16.f32 " \
                 "{%0,%1,%2,%3},{%4,%5,%6,%7},{%8,%9},{%0,%1,%2,%3};" \
                 : "+f"((d)[0]), "+f"((d)[1]), "+f"((d)[2]), "+f"((d)[3]) \
                 : "r"(a0), "r"(a1), "r"(a2), "r"(a3), "r"(b0), "r"(b1))

// bf16 slab: rows x 128B (64 bf16). SW128 over 16B slots, slot ^= (r&7).
__device__ __forceinline__ uint32_t soff16(int r, int c16) {
    return (uint32_t)(r * 128 + ((c16 ^ (r & 7)) * 16));
}

// exact int -> bf16 bits (|v| < 512 exact in bf16)
__device__ __forceinline__ uint16_t i2bf(int v) {
    return (uint16_t)(__float_as_uint((float)v) >> 16);
}

__device__ __forceinline__ uint32_t bfpair(int lo, int hi) {
    return (uint32_t)i2bf(lo) | ((uint32_t)i2bf(hi) << 16);
}

// ------------------------------ prepass ------------------------------------
// blocks [0,8192): pack X+25 (16B stores)
// blocks [8192,16384): pack+transpose Y-18 via 64k x 32n smem tiles (16B stores)

__global__ void k_pack_xy(const int4* __restrict__ qx, const int* __restrict__ Y) {
    __shared__ int8_t tile[64][36];
    if (blockIdx.x < 8192) {
        size_t i = (size_t)blockIdx.x * 256 + threadIdx.x;   // 8-elem group
        size_t e = i * 8;
        int m = (int)(e >> 12);
        int k = (int)(e & 4095);                             // multiple of 8
        int4 v0 = qx[i * 2];
        int4 v1 = qx[i * 2 + 1];
        uint4 w;
        w.x = bfpair(v0.x + 25, v0.y + 25);
        w.y = bfpair(v0.z + 25, v0.w + 25);
        w.z = bfpair(v1.x + 25, v1.y + 25);
        w.w = bfpair(v1.z + 25, v1.w + 25);
        size_t dst = ((size_t)(m >> 7) * 64 + (k >> 6)) * 16384
                   + soff16(m & 127, (k & 63) >> 3);
        *(uint4*)((char*)g_xa + dst) = w;
    } else {
        int bx = blockIdx.x - 8192;
        int n0 = (bx & 127) * 32;         // 128 n-blocks of 32
        int k0 = (bx >> 7) * 64;          // 64 k-blocks of 64
        int t = threadIdx.x;
        {
            int j0 = t * 2;
#pragma unroll
            for (int u = 0; u < 2; u++) {
                int j = j0 + u;                 // 0..511
                int kr = j >> 3;                // 8 int4 per k-row
                int nc = (j & 7) * 4;
                int4 v = *(const int4*)(Y + (size_t)(k0 + kr) * ND + n0 + nc);
                tile[kr][nc + 0] = (int8_t)v.x;
                tile[kr][nc + 1] = (int8_t)v.y;
                tile[kr][nc + 2] = (int8_t)v.z;
                tile[kr][nc + 3] = (int8_t)v.w;
            }
        }
        __syncthreads();
        {
            int nr = t >> 3;
            int kq = (t & 7) * 8;
            int n = n0 + nr;
            uint4 w;
            w.x = bfpair(tile[kq + 0][nr] - 18, tile[kq + 1][nr] - 18);
            w.y = bfpair(tile[kq + 2][nr] - 18, tile[kq + 3][nr] - 18);
            w.z = bfpair(tile[kq + 4][nr] - 18, tile[kq + 5][nr] - 18);
            w.w = bfpair(tile[kq + 6][nr] - 18, tile[kq + 7][nr] - 18);
            size_t dst = ((size_t)(n >> 7) * 64 + (k0 >> 6)) * 16384
                       + soff16(n & 127, kq >> 3);
            *(uint4*)((char*)g_yb + dst) = w;
        }
    }
}

// ------------------------------- GEMM -------------------------------------
// CTA tile 128(M) x 64(N); stage = A(16KB) + B(8KB) = 24KB; 3 stages + 1KB.
// 160 threads = 4 MMA warps (32 M-rows each) + 1 producer warp. 2 CTAs/SM.
// full[s] at +s*8 (tx), empty[s] at +32+s*8 (count 4, MMA warps only).

static constexpr int STAGES = 3;
static constexpr int STAGE_BYTES = 24576;
static constexpr int STAGE0_OFF = 1024;
static constexpr int SMEM_TOTAL = STAGE0_OFF + STAGES * STAGE_BYTES;  // 74752
static constexpr int KITERS = KD / 64;                                // 64

__global__ void __launch_bounds__(160, 2)
gemm_bf16_kernel(float* __restrict__ OUT) {
    extern __shared__ char smem[];
    const uint32_t sbase = smem_u32(smem);
    const uint32_t stg = sbase + STAGE0_OFF;
    const int tid = threadIdx.x;
    const int lane = tid & 31;
    const int wm = tid >> 5;                // 0..3 = MMA warps; 4 = producer
    const int m0 = blockIdx.y * 128;
    const int n0 = blockIdx.x * 64;

    const int sel = lane >> 3;              // ldmatrix matrix id
    const int l7  = lane & 7;

    const char* aslab = (const char*)g_xa + (size_t)(m0 >> 7) * 64 * 16384;
    const char* bslab = (const char*)g_yb + (size_t)(n0 >> 7) * 64 * 16384
                        + (size_t)(n0 & 64) * 128;   // 64-row half of the slab

    if (tid == 0) {
#pragma unroll
        for (int s = 0; s < STAGES; s++) {
            MBARRIER_INIT(sbase + s * 8, 1);            // full: tx-based
            MBARRIER_INIT(sbase + 32 + s * 8, 4);       // empty: 4 MMA warps
        }
        asm volatile("fence.proxy.async.shared::cta;" ::: "memory");
    }
    __syncthreads();

    if (wm == 4) {
        // ---------------- dedicated producer warp ----------------
        if (lane == 0) {
#pragma unroll
            for (int p = 0; p < STAGES; p++) {
                MBARRIER_EXPECT_TX(sbase + p * 8, STAGE_BYTES);
                bulk_g2s(stg + p * STAGE_BYTES,         aslab + (size_t)p * 16384, 16384, sbase + p * 8);
                bulk_g2s(stg + p * STAGE_BYTES + 16384, bslab + (size_t)p * 16384, 8192,  sbase + p * 8);
            }
            for (int it = 0; it + STAGES < KITERS; it++) {
                const int s = it % 3;
                const int ph = (it / 3) & 1;
                MBARRIER_WAIT_PARITY(sbase + 32 + s * 8, ph);   // empty[s] (acquire)
                MBARRIER_EXPECT_TX(sbase + s * 8, STAGE_BYTES);
                bulk_g2s(stg + s * STAGE_BYTES,         aslab + (size_t)(it + STAGES) * 16384, 16384, sbase + s * 8);
                bulk_g2s(stg + s * STAGE_BYTES + 16384, bslab + (size_t)(it + STAGES) * 16384, 8192,  sbase + s * 8);
            }
        }
        return;     // producer warp exits; CTA resources persist
    }

    // -------------------- MMA warps (wm 0..3) --------------------
    float acc[2][8][4];
#pragma unroll
    for (int i = 0; i < 2; i++)
#pragma unroll
        for (int j = 0; j < 8; j++)
#pragma unroll
            for (int q = 0; q < 4; q++) acc[i][j][q] = 0.0f;

    int s = 0, ph = 0;
    for (int it = 0; it < KITERS; it++) {
        MBARRIER_WAIT_PARITY(sbase + s * 8, ph);        // full[s]

        const uint32_t sA = stg + s * STAGE_BYTES;
        const uint32_t sB = sA + 16384;

#pragma unroll
        for (int kq = 0; kq < 4; kq++) {          // 4 x k16 per stage
            uint32_t a[2][4];
#pragma unroll
            for (int mt = 0; mt < 2; mt++) {
                int row = wm * 32 + mt * 16 + l7 + (sel & 1) * 8;
                int c16 = kq * 2 + (sel >> 1);
                LDSM4(a[mt][0], a[mt][1], a[mt][2], a[mt][3], sA + soff16(row, c16));
            }
            uint32_t b[4][4];
#pragma unroll
            for (int np = 0; np < 4; np++) {
                int row = np * 16 + (sel >> 1) * 8 + l7;       // 0..63
                int c16 = kq * 2 + (sel & 1);
                LDSM4(b[np][0], b[np][1], b[np][2], b[np][3], sB + soff16(row, c16));
            }
#pragma unroll
            for (int np = 0; np < 4; np++) {
                MMA_BF16(acc[0][np * 2 + 0], a[0][0], a[0][1], a[0][2], a[0][3],
                         b[np][0], b[np][1]);
                MMA_BF16(acc[0][np * 2 + 1], a[0][0], a[0][1], a[0][2], a[0][3],
                         b[np][2], b[np][3]);
                MMA_BF16(acc[1][np * 2 + 0], a[1][0], a[1][1], a[1][2], a[1][3],
                         b[np][0], b[np][1]);
                MMA_BF16(acc[1][np * 2 + 1], a[1][0], a[1][1], a[1][2], a[1][3],
                         b[np][2], b[np][3]);
            }
        }

        // warp done reading stage s -> release it to the producer
        if (lane == 0) MBARRIER_ARRIVE(sbase + 32 + s * 8);
        if (++s == STAGES) { s = 0; ph ^= 1; }
    }

    // epilogue: pure scale, no corrections
    const int gid = lane >> 2, tig = lane & 3;
#pragma unroll
    for (int mt = 0; mt < 2; mt++) {
#pragma unroll
        for (int h = 0; h < 2; h++) {
            const int rloc = wm * 32 + mt * 16 + h * 8 + gid;
            float* orow = OUT + (size_t)(m0 + rloc) * ND + n0 + tig * 2;
#pragma unroll
            for (int nt = 0; nt < 8; nt++) {
                float2 v;
                v.x = SXY * acc[mt][nt][h * 2 + 0];
                v.y = SXY * acc[mt][nt][h * 2 + 1];
                *(float2*)(orow + nt * 8) = v;
            }
        }
    }
}

// ------------------------------- launch ------------------------------------

extern "C" void kernel_launch(void* const* d_in, const int* in_sizes, int n_in,
                              void* d_out, int out_size) {
    const int* X32 = (const int*)d_in[0];
    const int* Y32 = (const int*)d_in[1];
    float* OUT = (float*)d_out;

    cudaFuncSetAttribute(gemm_bf16_kernel,
                         cudaFuncAttributeMaxDynamicSharedMemorySize, SMEM_TOTAL);

    k_pack_xy<<<16384, 256>>>((const int4*)X32, Y32);
    gemm_bf16_kernel<<<dim3(ND / 64, MD / 128), 160, SMEM_TOTAL>>>(OUT);
}

// round 17
// speedup vs baseline: 3.2169x; 1.0006x over previous
#include <cuda_runtime.h>
#include <cstdint>

// ---------------------------------------------------------------------------
// out = sx*sy * ( (X+25) @ (Y-18) )   [zero-points folded into bf16 pack]
// Inputs are INT32 (harness canonical), values in [-128,127].
// Engine: legacy bf16 HMMA (m16n8k16.f32.bf16.bf16.f32); ints exact in bf16.
// Prepass packs PRE-SWIZZLED bf16 slabs (16KB per 128x64 tile), 16B stores.
// GEMM: 128(M)x64(N) CTA tile, K-stage 64, 3-stage cp.async.bulk pipeline.
// Block = 160 threads: 4 MMA warps + 1 dedicated producer warp. 2 CTAs/SM.
// RACE FIX vs R16: empty barriers count=128 and ALL consumer lanes arrive
// (a release-arrive only orders the arriving thread's own reads; lane0-only
// arrives left 31/32 lanes' LDSM reads unordered vs the refill write).
// ---------------------------------------------------------------------------

static constexpr int MD = 4096, KD = 4096, ND = 4096;
static constexpr float SXY = 0.0215f * 0.0176f;

__device__ uint16_t g_xa[(size_t)MD * KD];     // 32MB bf16 tiled swizzled (X+25)
__device__ uint16_t g_yb[(size_t)ND * KD];     // 32MB bf16 tiled swizzled (Y-18)^T

// ------------------------------ helpers -----------------------------------

__device__ __forceinline__ uint32_t smem_u32(const void* p) {
    uint32_t a;
    asm("{ .reg .u64 t; cvta.to.shared.u64 t, %1; cvt.u32.u64 %0, t; }"
        : "=r"(a) : "l"(p));
    return a;
}

#define MBARRIER_INIT(addr, cnt) \
    asm volatile("mbarrier.init.shared.b64 [%0], %1;" :: "r"(addr), "r"(cnt) : "memory")

#define MBARRIER_ARRIVE_RELEASE(addr) \
    asm volatile("mbarrier.arrive.release.cta.shared::cta.b64 _, [%0];" \
                 :: "r"(addr) : "memory")

#define MBARRIER_EXPECT_TX(addr, bytes) \
    asm volatile("mbarrier.arrive.expect_tx.shared.b64 _, [%0], %1;" \
                 :: "r"(addr), "r"(bytes) : "memory")

#define MBARRIER_WAIT_PARITY(addr, ph) do {                                         \
    uint32_t _m = (uint32_t)(addr); uint32_t _p = (uint32_t)(ph); uint32_t _d;      \
    asm volatile("{\n\t.reg .pred p;\n\t"                                           \
        "mbarrier.try_wait.parity.acquire.cta.shared::cta.b64 p, [%1], %2;\n\t"     \
        "selp.b32 %0, 1, 0, p;\n\t}"                                                \
        : "=r"(_d) : "r"(_m), "r"(_p) : "memory");                                  \
    if (!_d) {                                                                      \
        asm volatile("{\n\t.reg .pred P1;\n\t"                                      \
            "WL%=:\n\t"                                                             \
            "mbarrier.try_wait.parity.acquire.cta.shared::cta.b64 P1, [%0], %1, 0x989680;\n\t" \
            "@P1 bra.uni WD%=;\n\t"                                                 \
            "bra.uni WL%=;\n\t"                                                     \
            "WD%=:\n\t}"                                                            \
            :: "r"(_m), "r"(_p) : "memory");                                        \
    } } while (0)

__device__ __forceinline__ void bulk_g2s(uint32_t dst, const void* src,
                                         uint32_t bytes, uint32_t mbar) {
    asm volatile(
        "cp.async.bulk.shared::cluster.global.mbarrier::complete_tx::bytes "
        "[%0], [%1], %2, [%3];"
        :: "r"(dst), "l"(src), "r"(bytes), "r"(mbar) : "memory");
}

#define LDSM4(r0, r1, r2, r3, addr) \
    asm volatile("ldmatrix.sync.aligned.m8n8.x4.shared.b16 {%0,%1,%2,%3}, [%4];" \
                 : "=r"(r0), "=r"(r1), "=r"(r2), "=r"(r3) : "r"(addr))

#define MMA_BF16(d, a0, a1, a2, a3, b0, b1) \
    asm volatile("mma.sync.aligned.m16n8k16.row.col.f32.bf16.bf16.f32 " \
                 "{%0,%1,%2,%3},{%4,%5,%6,%7},{%8,%9},{%0,%1,%2,%3};" \
                 : "+f"((d)[0]), "+f"((d)[1]), "+f"((d)[2]), "+f"((d)[3]) \
                 : "r"(a0), "r"(a1), "r"(a2), "r"(a3), "r"(b0), "r"(b1))

// bf16 slab: rows x 128B (64 bf16). SW128 over 16B slots, slot ^= (r&7).
__device__ __forceinline__ uint32_t soff16(int r, int c16) {
    return (uint32_t)(r * 128 + ((c16 ^ (r & 7)) * 16));
}

// exact int -> bf16 bits (|v| < 512 exact in bf16)
__device__ __forceinline__ uint16_t i2bf(int v) {
    return (uint16_t)(__float_as_uint((float)v) >> 16);
}

__device__ __forceinline__ uint32_t bfpair(int lo, int hi) {
    return (uint32_t)i2bf(lo) | ((uint32_t)i2bf(hi) << 16);
}

// ------------------------------ prepass ------------------------------------
// blocks [0,8192): pack X+25 (16B stores)
// blocks [8192,16384): pack+transpose Y-18 via 64k x 32n smem tiles (16B stores)

__global__ void k_pack_xy(const int4* __restrict__ qx, const int* __restrict__ Y) {
    __shared__ int8_t tile[64][36];
    if (blockIdx.x < 8192) {
        size_t i = (size_t)blockIdx.x * 256 + threadIdx.x;   // 8-elem group
        size_t e = i * 8;
        int m = (int)(e >> 12);
        int k = (int)(e & 4095);                             // multiple of 8
        int4 v0 = qx[i * 2];
        int4 v1 = qx[i * 2 + 1];
        uint4 w;
        w.x = bfpair(v0.x + 25, v0.y + 25);
        w.y = bfpair(v0.z + 25, v0.w + 25);
        w.z = bfpair(v1.x + 25, v1.y + 25);
        w.w = bfpair(v1.z + 25, v1.w + 25);
        size_t dst = ((size_t)(m >> 7) * 64 + (k >> 6)) * 16384
                   + soff16(m & 127, (k & 63) >> 3);
        *(uint4*)((char*)g_xa + dst) = w;
    } else {
        int bx = blockIdx.x - 8192;
        int n0 = (bx & 127) * 32;         // 128 n-blocks of 32
        int k0 = (bx >> 7) * 64;          // 64 k-blocks of 64
        int t = threadIdx.x;
        {
            int j0 = t * 2;
#pragma unroll
            for (int u = 0; u < 2; u++) {
                int j = j0 + u;                 // 0..511
                int kr = j >> 3;                // 8 int4 per k-row
                int nc = (j & 7) * 4;
                int4 v = *(const int4*)(Y + (size_t)(k0 + kr) * ND + n0 + nc);
                tile[kr][nc + 0] = (int8_t)v.x;
                tile[kr][nc + 1] = (int8_t)v.y;
                tile[kr][nc + 2] = (int8_t)v.z;
                tile[kr][nc + 3] = (int8_t)v.w;
            }
        }
        __syncthreads();
        {
            int nr = t >> 3;
            int kq = (t & 7) * 8;
            int n = n0 + nr;
            uint4 w;
            w.x = bfpair(tile[kq + 0][nr] - 18, tile[kq + 1][nr] - 18);
            w.y = bfpair(tile[kq + 2][nr] - 18, tile[kq + 3][nr] - 18);
            w.z = bfpair(tile[kq + 4][nr] - 18, tile[kq + 5][nr] - 18);
            w.w = bfpair(tile[kq + 6][nr] - 18, tile[kq + 7][nr] - 18);
            size_t dst = ((size_t)(n >> 7) * 64 + (k0 >> 6)) * 16384
                       + soff16(n & 127, kq >> 3);
            *(uint4*)((char*)g_yb + dst) = w;
        }
    }
}

// ------------------------------- GEMM -------------------------------------
// CTA tile 128(M) x 64(N); stage = A(16KB) + B(8KB) = 24KB; 3 stages + 1KB.
// 160 threads = 4 MMA warps (32 M-rows each) + 1 producer warp. 2 CTAs/SM.
// full[s] at +s*8 (tx), empty[s] at +32+s*8 (count 128, ALL consumer lanes).

static constexpr int STAGES = 3;
static constexpr int STAGE_BYTES = 24576;
static constexpr int STAGE0_OFF = 1024;
static constexpr int SMEM_TOTAL = STAGE0_OFF + STAGES * STAGE_BYTES;  // 74752
static constexpr int KITERS = KD / 64;                                // 64

__global__ void __launch_bounds__(160, 2)
gemm_bf16_kernel(float* __restrict__ OUT) {
    extern __shared__ char smem[];
    const uint32_t sbase = smem_u32(smem);
    const uint32_t stg = sbase + STAGE0_OFF;
    const int tid = threadIdx.x;
    const int lane = tid & 31;
    const int wm = tid >> 5;                // 0..3 = MMA warps; 4 = producer
    const int m0 = blockIdx.y * 128;
    const int n0 = blockIdx.x * 64;

    const int sel = lane >> 3;              // ldmatrix matrix id
    const int l7  = lane & 7;

    const char* aslab = (const char*)g_xa + (size_t)(m0 >> 7) * 64 * 16384;
    const char* bslab = (const char*)g_yb + (size_t)(n0 >> 7) * 64 * 16384
                        + (size_t)(n0 & 64) * 128;   // 64-row half of the slab

    if (tid == 0) {
#pragma unroll
        for (int s = 0; s < STAGES; s++) {
            MBARRIER_INIT(sbase + s * 8, 1);            // full: tx-based
            MBARRIER_INIT(sbase + 32 + s * 8, 128);     // empty: all 128 lanes
        }
        asm volatile("fence.proxy.async.shared::cta;" ::: "memory");
    }
    __syncthreads();

    if (wm == 4) {
        // ---------------- dedicated producer warp ----------------
        if (lane == 0) {
#pragma unroll
            for (int p = 0; p < STAGES; p++) {
                MBARRIER_EXPECT_TX(sbase + p * 8, STAGE_BYTES);
                bulk_g2s(stg + p * STAGE_BYTES,         aslab + (size_t)p * 16384, 16384, sbase + p * 8);
                bulk_g2s(stg + p * STAGE_BYTES + 16384, bslab + (size_t)p * 16384, 8192,  sbase + p * 8);
            }
            for (int it = 0; it + STAGES < KITERS; it++) {
                const int s = it % 3;
                const int ph = (it / 3) & 1;
                MBARRIER_WAIT_PARITY(sbase + 32 + s * 8, ph);   // empty[s] (acquire)
                MBARRIER_EXPECT_TX(sbase + s * 8, STAGE_BYTES);
                bulk_g2s(stg + s * STAGE_BYTES,         aslab + (size_t)(it + STAGES) * 16384, 16384, sbase + s * 8);
                bulk_g2s(stg + s * STAGE_BYTES + 16384, bslab + (size_t)(it + STAGES) * 16384, 8192,  sbase + s * 8);
            }
        }
        return;     // producer warp exits
    }

    // -------------------- MMA warps (wm 0..3) --------------------
    float acc[2][8][4];
#pragma unroll
    for (int i = 0; i < 2; i++)
#pragma unroll
        for (int j = 0; j < 8; j++)
#pragma unroll
            for (int q = 0; q < 4; q++) acc[i][j][q] = 0.0f;

    int s = 0, ph = 0;
    for (int it = 0; it < KITERS; it++) {
        MBARRIER_WAIT_PARITY(sbase + s * 8, ph);        // full[s]

        const uint32_t sA = stg + s * STAGE_BYTES;
        const uint32_t sB = sA + 16384;

#pragma unroll
        for (int kq = 0; kq < 4; kq++) {          // 4 x k16 per stage
            uint32_t a[2][4];
#pragma unroll
            for (int mt = 0; mt < 2; mt++) {
                int row = wm * 32 + mt * 16 + l7 + (sel & 1) * 8;
                int c16 = kq * 2 + (sel >> 1);
                LDSM4(a[mt][0], a[mt][1], a[mt][2], a[mt][3], sA + soff16(row, c16));
            }
            uint32_t b[4][4];
#pragma unroll
            for (int np = 0; np < 4; np++) {
                int row = np * 16 + (sel >> 1) * 8 + l7;       // 0..63
                int c16 = kq * 2 + (sel & 1);
                LDSM4(b[np][0], b[np][1], b[np][2], b[np][3], sB + soff16(row, c16));
            }
#pragma unroll
            for (int np = 0; np < 4; np++) {
                MMA_BF16(acc[0][np * 2 + 0], a[0][0], a[0][1], a[0][2], a[0][3],
                         b[np][0], b[np][1]);
                MMA_BF16(acc[0][np * 2 + 1], a[0][0], a[0][1], a[0][2], a[0][3],
                         b[np][2], b[np][3]);
                MMA_BF16(acc[1][np * 2 + 0], a[1][0], a[1][1], a[1][2], a[1][3],
                         b[np][0], b[np][1]);
                MMA_BF16(acc[1][np * 2 + 1], a[1][0], a[1][1], a[1][2], a[1][3],
                         b[np][2], b[np][3]);
            }
        }

        // EVERY lane releases stage s: per-thread release-arrive orders
        // this thread's LDSM reads before the producer's refill write.
        MBARRIER_ARRIVE_RELEASE(sbase + 32 + s * 8);
        if (++s == STAGES) { s = 0; ph ^= 1; }
    }

    // epilogue: pure scale, no corrections
    const int gid = lane >> 2, tig = lane & 3;
#pragma unroll
    for (int mt = 0; mt < 2; mt++) {
#pragma unroll
        for (int h = 0; h < 2; h++) {
            const int rloc = wm * 32 + mt * 16 + h * 8 + gid;
            float* orow = OUT + (size_t)(m0 + rloc) * ND + n0 + tig * 2;
#pragma unroll
            for (int nt = 0; nt < 8; nt++) {
                float2 v;
                v.x = SXY * acc[mt][nt][h * 2 + 0];
                v.y = SXY * acc[mt][nt][h * 2 + 1];
                *(float2*)(orow + nt * 8) = v;
            }
        }
    }
}

// ------------------------------- launch ------------------------------------

extern "C" void kernel_launch(void* const* d_in, const int* in_sizes, int n_in,
                              void* d_out, int out_size) {
    const int* X32 = (const int*)d_in[0];
    const int* Y32 = (const int*)d_in[1];
    float* OUT = (float*)d_out;

    cudaFuncSetAttribute(gemm_bf16_kernel,
                         cudaFuncAttributeMaxDynamicSharedMemorySize, SMEM_TOTAL);

    k_pack_xy<<<16384, 256>>>((const int4*)X32, Y32);
    gemm_bf16_kernel<<<dim3(ND / 64, MD / 128), 160, SMEM_TOTAL>>>(OUT);
}